// round 6
// baseline (speedup 1.0000x reference)
#include <cuda_runtime.h>
#include <cuda_bf16.h>
#include <stdint.h>
#include <math.h>

// ---------------- problem constants ----------------
#define B_    2
#define NQ_   5376
#define NV_   5376
#define C_    256
#define HEADS_ 8
#define HD_   32
#define NPT   12
#define KD    256
#define MR    10752       // B*NQ

// ---------------- scratch ----------------
__device__ float g_v[(size_t)MR * C_];                 // GEMM1 out (fp32, gathered)
__device__ float g_off[(size_t)MR * 192];
__device__ float g_attn[(size_t)MR * 96];
__device__ __nv_bfloat16 g_val_hi[(size_t)MR * C_];    // value split
__device__ __nv_bfloat16 g_val_lo[(size_t)MR * C_];
__device__ __nv_bfloat16 g_q_hi[(size_t)MR * C_];      // query split
__device__ __nv_bfloat16 g_q_lo[(size_t)MR * C_];
__device__ __nv_bfloat16 g_tmp_hi[(size_t)MR * C_];    // sampled out split
__device__ __nv_bfloat16 g_tmp_lo[(size_t)MR * C_];
__device__ __nv_bfloat16 g_Wv_hi[256 * 256],  g_Wv_lo[256 * 256];
__device__ __nv_bfloat16 g_Wf_hi[192 * 256],  g_Wf_lo[192 * 256];
__device__ __nv_bfloat16 g_Wa_hi[96 * 256],   g_Wa_lo[96 * 256];
__device__ __nv_bfloat16 g_Wo_hi[256 * 256],  g_Wo_lo[256 * 256];

// ---------------- helpers ----------------
__device__ __forceinline__ uint32_t smem_u32(const void* p) {
    uint32_t a;
    asm("{ .reg .u64 t; cvta.to.shared.u64 t, %1; cvt.u32.u64 %0, t; }" : "=r"(a) : "l"(p));
    return a;
}
__device__ __forceinline__ uint32_t pack_bf2(float x, float y) {
    uint32_t r;
    asm("cvt.rn.bf16x2.f32 %0, %1, %2;" : "=r"(r) : "f"(y), "f"(x));
    return r;
}
__device__ __forceinline__ void split4(float4 v, uint2& hp, uint2& lp) {
    const uint32_t h01 = pack_bf2(v.x, v.y);
    const uint32_t h23 = pack_bf2(v.z, v.w);
    const float hx = __uint_as_float(h01 << 16);
    const float hy = __uint_as_float(h01 & 0xFFFF0000u);
    const float hz = __uint_as_float(h23 << 16);
    const float hw = __uint_as_float(h23 & 0xFFFF0000u);
    hp = make_uint2(h01, h23);
    lp = make_uint2(pack_bf2(v.x - hx, v.y - hy), pack_bf2(v.z - hz, v.w - hw));
}

#define LDM4(r, addr) \
    asm volatile("ldmatrix.sync.aligned.m8n8.x4.shared.b16 {%0,%1,%2,%3}, [%4];" \
        : "=r"((r)[0]), "=r"((r)[1]), "=r"((r)[2]), "=r"((r)[3]) : "r"(addr))

#define MMA_BF16(d, a, b0, b1) \
    asm volatile("mma.sync.aligned.m16n8k16.row.col.f32.bf16.bf16.f32 " \
        "{%0,%1,%2,%3}, {%4,%5,%6,%7}, {%8,%9}, {%0,%1,%2,%3};" \
        : "+f"((d)[0]), "+f"((d)[1]), "+f"((d)[2]), "+f"((d)[3]) \
        : "r"((a)[0]), "r"((a)[1]), "r"((a)[2]), "r"((a)[3]), "r"(b0), "r"(b1))

#define CPA(dst, src, sz) \
    asm volatile("cp.async.cg.shared.global [%0], [%1], 16, %2;" \
        :: "r"(dst), "l"(src), "r"(sz) : "memory")

// ---------------- convert: fp32 -> bf16 hi/lo ----------------
__global__ __launch_bounds__(256)
void cvt_split(const float* __restrict__ src, __nv_bfloat16* __restrict__ hi,
               __nv_bfloat16* __restrict__ lo, int n4)
{
    const int i = blockIdx.x * blockDim.x + threadIdx.x;
    if (i >= n4) return;
    uint2 hp, lp;
    split4(((const float4*)src)[i], hp, lp);
    ((uint2*)hi)[i] = hp;
    ((uint2*)lo)[i] = lp;
}

// ---------------- split-bf16 mma.sync GEMM, pre-split inputs ----------------
// C[M, Ntrue] = A[M,256] @ W[Ntrue,256]^T + bias (bf16 hi/lo in, fp32 out)
// BM=128, BN=128, BK=32, 256 threads (8 warps, 4x2, 32x64 warp tile), S_=40
#define S_ 40

__global__ __launch_bounds__(256)
void gemm_bf(const __nv_bfloat16* __restrict__ Ahi, const __nv_bfloat16* __restrict__ Alo,
             const __nv_bfloat16* __restrict__ Whi, const __nv_bfloat16* __restrict__ Wlo,
             const float* __restrict__ bias, float* __restrict__ Cc, int Ntrue)
{
    __shared__ __align__(16) __nv_bfloat16 sAhi[128 * S_];
    __shared__ __align__(16) __nv_bfloat16 sAlo[128 * S_];
    __shared__ __align__(16) __nv_bfloat16 sWhi[128 * S_];
    __shared__ __align__(16) __nv_bfloat16 sWlo[128 * S_];

    const int tid  = threadIdx.x;
    const int wid  = tid >> 5;
    const int lane = tid & 31;
    const int wm   = wid >> 1;
    const int wn   = wid & 1;
    const int bm   = blockIdx.y * 128;
    const int bn   = blockIdx.x * 128;
    const int wrows = Ntrue - bn;

    const uint32_t uAhi = smem_u32(sAhi);
    const uint32_t uAlo = smem_u32(sAlo);
    const uint32_t uWhi = smem_u32(sWhi);
    const uint32_t uWlo = smem_u32(sWlo);

    float acc[2][8][4];
    #pragma unroll
    for (int i = 0; i < 2; i++)
        #pragma unroll
        for (int j = 0; j < 8; j++)
            #pragma unroll
            for (int k = 0; k < 4; k++) acc[i][j][k] = 0.f;

    const int a_row = lane & 15;
    const int a_kc  = (lane & 16) ? 8 : 0;
    const int b_row = (lane & 7) + ((lane & 16) ? 8 : 0);
    const int b_kc  = (lane & 8) ? 8 : 0;

    for (int k0 = 0; k0 < KD; k0 += 32) {
        __syncthreads();
        // ---- stage via cp.async: 512 x 16B chunks per tile, 2 per thread ----
        #pragma unroll
        for (int i = 0; i < 2; i++) {
            const int f   = tid + i * 256;       // 0..511
            const int row = f >> 2;              // 0..127
            const int col = (f & 3) << 3;        // 0,8,16,24
            const uint32_t sdst = (row * S_ + col) * 2;
            const size_t aoff = (size_t)(bm + row) * KD + k0 + col;
            CPA(uAhi + sdst, Ahi + aoff, 16);
            CPA(uAlo + sdst, Alo + aoff, 16);
            const int valid = (row < wrows) ? 16 : 0;
            const int srow  = (row < wrows) ? row : 0;
            const size_t woff = (size_t)(bn + srow) * KD + k0 + col;
            CPA(uWhi + sdst, Whi + woff, valid);
            CPA(uWlo + sdst, Wlo + woff, valid);
        }
        asm volatile("cp.async.commit_group;" ::: "memory");
        asm volatile("cp.async.wait_group 0;" ::: "memory");
        __syncthreads();

        // ---- compute: 2 k-steps of 16 ----
        #pragma unroll
        for (int ks = 0; ks < 2; ks++) {
            const int kb = ks * 16;
            uint32_t ah[2][4], al[2][4];
            #pragma unroll
            for (int mf = 0; mf < 2; mf++) {
                const int e = (wm * 32 + mf * 16 + a_row) * S_ + kb + a_kc;
                LDM4(ah[mf], uAhi + e * 2);
                LDM4(al[mf], uAlo + e * 2);
            }
            #pragma unroll
            for (int nf = 0; nf < 4; nf++) {
                uint32_t bh[4], bl[4];
                const int e = (wn * 64 + nf * 16 + b_row) * S_ + kb + b_kc;
                LDM4(bh, uWhi + e * 2);
                LDM4(bl, uWlo + e * 2);
                #pragma unroll
                for (int mf = 0; mf < 2; mf++) {
                    MMA_BF16(acc[mf][nf * 2 + 0], ah[mf], bh[0], bh[1]);
                    MMA_BF16(acc[mf][nf * 2 + 1], ah[mf], bh[2], bh[3]);
                    MMA_BF16(acc[mf][nf * 2 + 0], ah[mf], bl[0], bl[1]);
                    MMA_BF16(acc[mf][nf * 2 + 1], ah[mf], bl[2], bl[3]);
                    MMA_BF16(acc[mf][nf * 2 + 0], al[mf], bh[0], bh[1]);
                    MMA_BF16(acc[mf][nf * 2 + 1], al[mf], bh[2], bh[3]);
                }
            }
        }
    }

    // ---- epilogue ----
    const int grp  = lane >> 2;
    const int tid4 = lane & 3;
    #pragma unroll
    for (int mf = 0; mf < 2; mf++) {
        const int row0 = bm + wm * 32 + mf * 16 + grp;
        #pragma unroll
        for (int nf = 0; nf < 8; nf++) {
            const int gn = bn + wn * 64 + nf * 8 + tid4 * 2;
            if (gn < Ntrue) {
                const float bb0 = bias[gn];
                const float bb1 = bias[gn + 1];
                *(float2*)&Cc[(size_t)row0 * Ntrue + gn] =
                    make_float2(acc[mf][nf][0] + bb0, acc[mf][nf][1] + bb1);
                *(float2*)&Cc[(size_t)(row0 + 8) * Ntrue + gn] =
                    make_float2(acc[mf][nf][2] + bb0, acc[mf][nf][3] + bb1);
            }
        }
    }
}

// ---------------- fused sampling ----------------
// warp = (bq, head). lanes 0..11 prep; gather: lane = corner(2b) x chgroup(3b)
// output written as split bf16 hi/lo (feeds GEMM5 directly)
__global__ __launch_bounds__(256)
void msda_sample(const float* __restrict__ v, const float* __restrict__ ref,
                 const float* __restrict__ offp, const float* __restrict__ attn,
                 __nv_bfloat16* __restrict__ out_hi, __nv_bfloat16* __restrict__ out_lo)
{
    __shared__ int   si[8][NPT][4];
    __shared__ float swt[8][NPT][4];
    const int wslot = threadIdx.x >> 5;
    const int lane  = threadIdx.x & 31;
    const int warp  = blockIdx.x * 8 + wslot;
    const int head  = warp & 7;
    const int bq    = warp >> 3;
    const int b     = bq / NQ_;

    float lg = -1e30f;
    if (lane < NPT) lg = attn[(size_t)bq * 96 + head * NPT + lane];
    float mx = lg;
    #pragma unroll
    for (int o = 16; o; o >>= 1) mx = fmaxf(mx, __shfl_xor_sync(0xFFFFFFFFu, mx, o));
    float e = (lane < NPT) ? __expf(lg - mx) : 0.f;
    float s = e;
    #pragma unroll
    for (int o = 16; o; o >>= 1) s += __shfl_xor_sync(0xFFFFFFFFu, s, o);

    if (lane < NPT) {
        const float aw  = e / s;
        const int lvl   = lane >> 2;
        const int Hs    = 64 >> lvl;
        const int Wsz   = Hs;
        const int start = (lvl == 0) ? 0 : (lvl == 1) ? 4096 : 5120;
        const float rx = ref[(size_t)bq * 2 + 0];
        const float ry = ref[(size_t)bq * 2 + 1];
        const float ox = offp[(size_t)bq * 192 + head * 24 + lane * 2 + 0];
        const float oy = offp[(size_t)bq * 192 + head * 24 + lane * 2 + 1];
        const float lx = fminf(fmaxf(rx + ox, 0.f), 1.f);
        const float ly = fminf(fmaxf(ry + oy, 0.f), 1.f);
        const float x = lx * (float)Wsz - 0.5f;
        const float y = ly * (float)Hs - 0.5f;
        const float x0f = floorf(x);
        const float y0f = floorf(y);
        const float wx1 = x - x0f;
        const float wy1 = y - y0f;
        const int x0 = (int)x0f;
        const int y0 = (int)y0f;
        const int vb = (b * NV_ + start) * C_ + head * HD_;
        #pragma unroll
        for (int dy = 0; dy < 2; dy++) {
            #pragma unroll
            for (int dx = 0; dx < 2; dx++) {
                const int ix = x0 + dx;
                const int iy = y0 + dy;
                const float w = (dx ? wx1 : 1.f - wx1) * (dy ? wy1 : 1.f - wy1);
                const bool valid = (ix >= 0) & (ix < Wsz) & (iy >= 0) & (iy < Hs);
                const int cx = min(max(ix, 0), Wsz - 1);
                const int cy = min(max(iy, 0), Hs - 1);
                si[wslot][lane][dy * 2 + dx]  = vb + (cy * Wsz + cx) * C_;
                swt[wslot][lane][dy * 2 + dx] = valid ? (w * aw) : 0.f;
            }
        }
    }
    __syncwarp();

    const int c = lane >> 3;      // corner 0..3
    const int g = lane & 7;       // channel group (4 ch)
    float4 acc = make_float4(0.f, 0.f, 0.f, 0.f);
    #pragma unroll
    for (int p = 0; p < NPT; p++) {
        const int   idx = si[wslot][p][c];
        const float w   = swt[wslot][p][c];
        const float4 val = __ldg((const float4*)(v + idx) + g);
        acc.x = fmaf(w, val.x, acc.x);
        acc.y = fmaf(w, val.y, acc.y);
        acc.z = fmaf(w, val.z, acc.z);
        acc.w = fmaf(w, val.w, acc.w);
    }
    // reduce over corners (lanes g, g+8, g+16, g+24)
    #pragma unroll
    for (int o = 8; o <= 16; o <<= 1) {
        acc.x += __shfl_xor_sync(0xFFFFFFFFu, acc.x, o);
        acc.y += __shfl_xor_sync(0xFFFFFFFFu, acc.y, o);
        acc.z += __shfl_xor_sync(0xFFFFFFFFu, acc.z, o);
        acc.w += __shfl_xor_sync(0xFFFFFFFFu, acc.w, o);
    }
    if (c == 0) {
        uint2 hp, lp;
        split4(acc, hp, lp);
        const size_t eo = ((size_t)bq * C_ + head * HD_ + g * 4) >> 2;
        ((uint2*)out_hi)[eo] = hp;
        ((uint2*)out_lo)[eo] = lp;
    }
}

// ---------------- launch ----------------
extern "C" void kernel_launch(void* const* d_in, const int* in_sizes, int n_in,
                              void* d_out, int out_size)
{
    const float* query = (const float*)d_in[0];
    const float* refp  = (const float*)d_in[1];
    const float* value = (const float*)d_in[2];
    const float* Wv    = (const float*)d_in[3];
    const float* bv    = (const float*)d_in[4];
    const float* Woff  = (const float*)d_in[5];
    const float* boff  = (const float*)d_in[6];
    const float* Wa    = (const float*)d_in[7];
    const float* ba    = (const float*)d_in[8];
    const float* Wo    = (const float*)d_in[9];
    const float* bo    = (const float*)d_in[10];
    float* out = (float*)d_out;

    float *p_v, *p_off, *p_attn;
    __nv_bfloat16 *p_vh, *p_vl, *p_qh, *p_ql, *p_th, *p_tl;
    __nv_bfloat16 *p_Wvh, *p_Wvl, *p_Wfh, *p_Wfl, *p_Wah, *p_Wal, *p_Woh, *p_Wol;
    cudaGetSymbolAddress((void**)&p_v,    g_v);
    cudaGetSymbolAddress((void**)&p_off,  g_off);
    cudaGetSymbolAddress((void**)&p_attn, g_attn);
    cudaGetSymbolAddress((void**)&p_vh,   g_val_hi);
    cudaGetSymbolAddress((void**)&p_vl,   g_val_lo);
    cudaGetSymbolAddress((void**)&p_qh,   g_q_hi);
    cudaGetSymbolAddress((void**)&p_ql,   g_q_lo);
    cudaGetSymbolAddress((void**)&p_th,   g_tmp_hi);
    cudaGetSymbolAddress((void**)&p_tl,   g_tmp_lo);
    cudaGetSymbolAddress((void**)&p_Wvh,  g_Wv_hi);
    cudaGetSymbolAddress((void**)&p_Wvl,  g_Wv_lo);
    cudaGetSymbolAddress((void**)&p_Wfh,  g_Wf_hi);
    cudaGetSymbolAddress((void**)&p_Wfl,  g_Wf_lo);
    cudaGetSymbolAddress((void**)&p_Wah,  g_Wa_hi);
    cudaGetSymbolAddress((void**)&p_Wal,  g_Wa_lo);
    cudaGetSymbolAddress((void**)&p_Woh,  g_Wo_hi);
    cudaGetSymbolAddress((void**)&p_Wol,  g_Wo_lo);

    const dim3 blk(256);
    const int n4_big = MR * C_ / 4;          // 688128 / 4-vec

    // ---- converts ----
    cvt_split<<<(n4_big + 255) / 256, blk>>>(value, p_vh, p_vl, n4_big);
    cvt_split<<<(n4_big + 255) / 256, blk>>>(query, p_qh, p_ql, n4_big);
    cvt_split<<<(256 * 256 / 4 + 255) / 256, blk>>>(Wv,   p_Wvh, p_Wvl, 256 * 256 / 4);
    cvt_split<<<(192 * 256 / 4 + 255) / 256, blk>>>(Woff, p_Wfh, p_Wfl, 192 * 256 / 4);
    cvt_split<<<(96  * 256 / 4 + 255) / 256, blk>>>(Wa,   p_Wah, p_Wal, 96 * 256 / 4);
    cvt_split<<<(256 * 256 / 4 + 255) / 256, blk>>>(Wo,   p_Woh, p_Wol, 256 * 256 / 4);

    // ---- GEMMs ----
    gemm_bf<<<dim3(2, 84), blk>>>(p_vh, p_vl, p_Wvh, p_Wvl, bv,   p_v,    256);
    gemm_bf<<<dim3(2, 84), blk>>>(p_qh, p_ql, p_Wfh, p_Wfl, boff, p_off,  192);
    gemm_bf<<<dim3(1, 84), blk>>>(p_qh, p_ql, p_Wah, p_Wal, ba,   p_attn, 96);

    // ---- sampling (writes split bf16 tmp) ----
    msda_sample<<<(MR * HEADS_) / 8, blk>>>(p_v, refp, p_off, p_attn, p_th, p_tl);

    // ---- output GEMM ----
    gemm_bf<<<dim3(2, 84), blk>>>(p_th, p_tl, p_Woh, p_Wol, bo, out, 256);
}

// round 7
// speedup vs baseline: 1.3875x; 1.3875x over previous
#include <cuda_runtime.h>
#include <cuda_bf16.h>
#include <stdint.h>
#include <math.h>

// ---------------- problem constants ----------------
#define B_    2
#define NQ_   5376
#define NV_   5376
#define C_    256
#define HEADS_ 8
#define HD_   32
#define NPT   12
#define KD    256
#define MR    10752       // B*NQ
#define NFA   288         // 192 (off) + 96 (attn) fused

// ---------------- scratch ----------------
__device__ float g_v[(size_t)MR * C_];                 // value-proj out (fp32, gathered)
__device__ float g_oa[(size_t)MR * NFA];               // fused off(192)+attn(96) out
__device__ float g_bfa[NFA];                           // fused bias
__device__ __nv_bfloat16 g_val_hi[(size_t)MR * C_];
__device__ __nv_bfloat16 g_val_lo[(size_t)MR * C_];
__device__ __nv_bfloat16 g_q_hi[(size_t)MR * C_];
__device__ __nv_bfloat16 g_q_lo[(size_t)MR * C_];
__device__ __nv_bfloat16 g_tmp_hi[(size_t)MR * C_];
__device__ __nv_bfloat16 g_tmp_lo[(size_t)MR * C_];
__device__ __nv_bfloat16 g_Wv_hi[256 * 256],  g_Wv_lo[256 * 256];
__device__ __nv_bfloat16 g_Wfa_hi[NFA * 256], g_Wfa_lo[NFA * 256];
__device__ __nv_bfloat16 g_Wo_hi[256 * 256],  g_Wo_lo[256 * 256];

// ---------------- helpers ----------------
__device__ __forceinline__ uint32_t smem_u32(const void* p) {
    uint32_t a;
    asm("{ .reg .u64 t; cvta.to.shared.u64 t, %1; cvt.u32.u64 %0, t; }" : "=r"(a) : "l"(p));
    return a;
}
__device__ __forceinline__ uint32_t pack_bf2(float x, float y) {
    uint32_t r;
    asm("cvt.rn.bf16x2.f32 %0, %1, %2;" : "=r"(r) : "f"(y), "f"(x));
    return r;
}
__device__ __forceinline__ void split4(float4 v, uint2& hp, uint2& lp) {
    const uint32_t h01 = pack_bf2(v.x, v.y);
    const uint32_t h23 = pack_bf2(v.z, v.w);
    const float hx = __uint_as_float(h01 << 16);
    const float hy = __uint_as_float(h01 & 0xFFFF0000u);
    const float hz = __uint_as_float(h23 << 16);
    const float hw = __uint_as_float(h23 & 0xFFFF0000u);
    hp = make_uint2(h01, h23);
    lp = make_uint2(pack_bf2(v.x - hx, v.y - hy), pack_bf2(v.z - hz, v.w - hw));
}

#define LDM4(r, addr) \
    asm volatile("ldmatrix.sync.aligned.m8n8.x4.shared.b16 {%0,%1,%2,%3}, [%4];" \
        : "=r"((r)[0]), "=r"((r)[1]), "=r"((r)[2]), "=r"((r)[3]) : "r"(addr))

#define MMA_BF16(d, a, b0, b1) \
    asm volatile("mma.sync.aligned.m16n8k16.row.col.f32.bf16.bf16.f32 " \
        "{%0,%1,%2,%3}, {%4,%5,%6,%7}, {%8,%9}, {%0,%1,%2,%3};" \
        : "+f"((d)[0]), "+f"((d)[1]), "+f"((d)[2]), "+f"((d)[3]) \
        : "r"((a)[0]), "r"((a)[1]), "r"((a)[2]), "r"((a)[3]), "r"(b0), "r"(b1))

#define CPA(dst, src, sz) \
    asm volatile("cp.async.cg.shared.global [%0], [%1], 16, %2;" \
        :: "r"(dst), "l"(src), "r"(sz) : "memory")
#define CPCOMMIT() asm volatile("cp.async.commit_group;" ::: "memory")
#define CPWAIT(n)  asm volatile("cp.async.wait_group %0;" :: "n"(n) : "memory")

// ---------------- fused convert: all splits in ONE launch ----------------
// sections (float4 units):
//   [0, N0): value      [N0, N1): query
//   [N1, N2): Wv        [N2, N3): Woff -> Wfa[0:192]   [N3, N4): Wa -> Wfa[192:288]
//   [N4, N5): Wo        [N5, N6): bias concat (boff 48, ba 24)
#define CN0 (MR * C_ / 4)
#define CN1 (CN0 + MR * C_ / 4)
#define CN2 (CN1 + 256 * 256 / 4)
#define CN3 (CN2 + 192 * 256 / 4)
#define CN4 (CN3 + 96 * 256 / 4)
#define CN5 (CN4 + 256 * 256 / 4)
#define CN6 (CN5 + 72)

__global__ __launch_bounds__(256)
void cvt_all(const float* __restrict__ value, const float* __restrict__ query,
             const float* __restrict__ Wv, const float* __restrict__ Woff,
             const float* __restrict__ Wa, const float* __restrict__ Wo,
             const float* __restrict__ boff, const float* __restrict__ ba)
{
    const int i = blockIdx.x * blockDim.x + threadIdx.x;
    if (i >= CN6) return;

    const float4* src;
    __nv_bfloat16 *hi, *lo;
    int j;
    if (i < CN0)      { src = (const float4*)value; hi = g_val_hi; lo = g_val_lo; j = i; }
    else if (i < CN1) { src = (const float4*)query; hi = g_q_hi;   lo = g_q_lo;   j = i - CN0; }
    else if (i < CN2) { src = (const float4*)Wv;    hi = g_Wv_hi;  lo = g_Wv_lo;  j = i - CN1; }
    else if (i < CN3) { src = (const float4*)Woff;  hi = g_Wfa_hi; lo = g_Wfa_lo; j = i - CN2; }
    else if (i < CN4) { src = (const float4*)Wa;    hi = g_Wfa_hi + 192 * 256;
                        lo = g_Wfa_lo + 192 * 256;  j = i - CN3; }
    else if (i < CN5) { src = (const float4*)Wo;    hi = g_Wo_hi;  lo = g_Wo_lo;  j = i - CN4; }
    else {
        const int k = i - CN5;      // 0..71
        ((float4*)g_bfa)[k] = (k < 48) ? ((const float4*)boff)[k]
                                       : ((const float4*)ba)[k - 48];
        return;
    }
    uint2 hp, lp;
    split4(src[j], hp, lp);
    ((uint2*)hi)[j] = hp;
    ((uint2*)lo)[j] = lp;
}

// ---------------- split-bf16 mma.sync GEMM, 2-stage cp.async pipeline ----------------
// C[M, Ntrue] = A[M,256] @ W[Ntrue,256]^T + bias (bf16 hi/lo in, fp32 out)
// BM=128, BN=128, BK=32, 256 threads (8 warps, 4x2, 32x64 warp tile), S_=40
#define S_ 40
#define STG_B (128 * S_ * 2)           // one buffer: 10240 B
#define STAGE_B (4 * STG_B)            // Ahi,Alo,Whi,Wlo: 40960 B
#define GSMEM (2 * STAGE_B)            // 81920 B

__global__ __launch_bounds__(256)
void gemm_bf(const __nv_bfloat16* __restrict__ Ahi, const __nv_bfloat16* __restrict__ Alo,
             const __nv_bfloat16* __restrict__ Whi, const __nv_bfloat16* __restrict__ Wlo,
             const float* __restrict__ bias, float* __restrict__ Cc, int Ntrue)
{
    extern __shared__ __align__(16) char smem[];
    const int tid  = threadIdx.x;
    const int wid  = tid >> 5;
    const int lane = tid & 31;
    const int wm   = wid >> 1;
    const int wn   = wid & 1;
    const int bm   = blockIdx.y * 128;
    const int bn   = blockIdx.x * 128;
    const int wrows = Ntrue - bn;

    const uint32_t sb = smem_u32(smem);

    float acc[2][8][4];
    #pragma unroll
    for (int i = 0; i < 2; i++)
        #pragma unroll
        for (int j = 0; j < 8; j++)
            #pragma unroll
            for (int k = 0; k < 4; k++) acc[i][j][k] = 0.f;

    // staging: 512 x 16B chunks per array, 2 per thread
    const int srow = (tid + 0) >> 2;              // using f = tid and tid+256
    // (computed inline below)

    // prefetch macro body as lambda
    auto prefetch = [&](int ch, int stg) {
        const int k0 = ch * 32;
        const uint32_t base = sb + stg * STAGE_B;
        #pragma unroll
        for (int i = 0; i < 2; i++) {
            const int f   = tid + i * 256;        // 0..511
            const int row = f >> 2;               // 0..127
            const int col = (f & 3) << 3;         // 0,8,16,24
            const uint32_t sdst = (row * S_ + col) * 2;
            const size_t aoff = (size_t)(bm + row) * KD + k0 + col;
            CPA(base + 0 * STG_B + sdst, Ahi + aoff, 16);
            CPA(base + 1 * STG_B + sdst, Alo + aoff, 16);
            const int valid = (row < wrows) ? 16 : 0;
            const int wr    = (row < wrows) ? row : 0;
            const size_t woff = (size_t)(bn + wr) * KD + k0 + col;
            CPA(base + 2 * STG_B + sdst, Whi + woff, valid);
            CPA(base + 3 * STG_B + sdst, Wlo + woff, valid);
        }
        CPCOMMIT();
    };

    const int a_row = lane & 15;
    const int a_kc  = (lane & 16) ? 8 : 0;
    const int b_row = (lane & 7) + ((lane & 16) ? 8 : 0);
    const int b_kc  = (lane & 8) ? 8 : 0;

    prefetch(0, 0);

    #pragma unroll 1
    for (int ch = 0; ch < 8; ch++) {
        const int cur = ch & 1;
        if (ch < 7) {
            prefetch(ch + 1, cur ^ 1);
            CPWAIT(1);
        } else {
            CPWAIT(0);
        }
        __syncthreads();

        const uint32_t base = sb + cur * STAGE_B;
        const uint32_t uAhi = base;
        const uint32_t uAlo = base + STG_B;
        const uint32_t uWhi = base + 2 * STG_B;
        const uint32_t uWlo = base + 3 * STG_B;

        #pragma unroll
        for (int ks = 0; ks < 2; ks++) {
            const int kb = ks * 16;
            uint32_t ah[2][4], al[2][4];
            #pragma unroll
            for (int mf = 0; mf < 2; mf++) {
                const int e = (wm * 32 + mf * 16 + a_row) * S_ + kb + a_kc;
                LDM4(ah[mf], uAhi + e * 2);
                LDM4(al[mf], uAlo + e * 2);
            }
            #pragma unroll
            for (int nf = 0; nf < 4; nf++) {
                uint32_t bh[4], bl[4];
                const int e = (wn * 64 + nf * 16 + b_row) * S_ + kb + b_kc;
                LDM4(bh, uWhi + e * 2);
                LDM4(bl, uWlo + e * 2);
                #pragma unroll
                for (int mf = 0; mf < 2; mf++) {
                    MMA_BF16(acc[mf][nf * 2 + 0], ah[mf], bh[0], bh[1]);
                    MMA_BF16(acc[mf][nf * 2 + 1], ah[mf], bh[2], bh[3]);
                    MMA_BF16(acc[mf][nf * 2 + 0], ah[mf], bl[0], bl[1]);
                    MMA_BF16(acc[mf][nf * 2 + 1], ah[mf], bl[2], bl[3]);
                    MMA_BF16(acc[mf][nf * 2 + 0], al[mf], bh[0], bh[1]);
                    MMA_BF16(acc[mf][nf * 2 + 1], al[mf], bh[2], bh[3]);
                }
            }
        }
        __syncthreads();
    }

    // ---- epilogue ----
    const int grp  = lane >> 2;
    const int tid4 = lane & 3;
    #pragma unroll
    for (int mf = 0; mf < 2; mf++) {
        const int row0 = bm + wm * 32 + mf * 16 + grp;
        #pragma unroll
        for (int nf = 0; nf < 8; nf++) {
            const int gn = bn + wn * 64 + nf * 8 + tid4 * 2;
            if (gn < Ntrue) {
                const float bb0 = bias[gn];
                const float bb1 = bias[gn + 1];
                *(float2*)&Cc[(size_t)row0 * Ntrue + gn] =
                    make_float2(acc[mf][nf][0] + bb0, acc[mf][nf][1] + bb1);
                *(float2*)&Cc[(size_t)(row0 + 8) * Ntrue + gn] =
                    make_float2(acc[mf][nf][2] + bb0, acc[mf][nf][3] + bb1);
            }
        }
    }
}

// ---------------- fused sampling ----------------
// warp = (bq, head). lanes 0..11 prep; gather: lane = corner(2b) x chgroup(3b)
// reads off/attn from fused g_oa (stride 288); writes split bf16 tmp
__global__ __launch_bounds__(256)
void msda_sample(const float* __restrict__ v, const float* __restrict__ ref,
                 const float* __restrict__ oa,
                 __nv_bfloat16* __restrict__ out_hi, __nv_bfloat16* __restrict__ out_lo)
{
    __shared__ int   si[8][NPT][4];
    __shared__ float swt[8][NPT][4];
    const int wslot = threadIdx.x >> 5;
    const int lane  = threadIdx.x & 31;
    const int warp  = blockIdx.x * 8 + wslot;
    const int head  = warp & 7;
    const int bq    = warp >> 3;
    const int b     = bq / NQ_;

    float lg = -1e30f;
    if (lane < NPT) lg = oa[(size_t)bq * NFA + 192 + head * NPT + lane];
    float mx = lg;
    #pragma unroll
    for (int o = 16; o; o >>= 1) mx = fmaxf(mx, __shfl_xor_sync(0xFFFFFFFFu, mx, o));
    float e = (lane < NPT) ? __expf(lg - mx) : 0.f;
    float s = e;
    #pragma unroll
    for (int o = 16; o; o >>= 1) s += __shfl_xor_sync(0xFFFFFFFFu, s, o);

    if (lane < NPT) {
        const float aw  = e / s;
        const int lvl   = lane >> 2;
        const int Hs    = 64 >> lvl;
        const int Wsz   = Hs;
        const int start = (lvl == 0) ? 0 : (lvl == 1) ? 4096 : 5120;
        const float rx = ref[(size_t)bq * 2 + 0];
        const float ry = ref[(size_t)bq * 2 + 1];
        const float ox = oa[(size_t)bq * NFA + head * 24 + lane * 2 + 0];
        const float oy = oa[(size_t)bq * NFA + head * 24 + lane * 2 + 1];
        const float lx = fminf(fmaxf(rx + ox, 0.f), 1.f);
        const float ly = fminf(fmaxf(ry + oy, 0.f), 1.f);
        const float x = lx * (float)Wsz - 0.5f;
        const float y = ly * (float)Hs - 0.5f;
        const float x0f = floorf(x);
        const float y0f = floorf(y);
        const float wx1 = x - x0f;
        const float wy1 = y - y0f;
        const int x0 = (int)x0f;
        const int y0 = (int)y0f;
        const int vb = (b * NV_ + start) * C_ + head * HD_;
        #pragma unroll
        for (int dy = 0; dy < 2; dy++) {
            #pragma unroll
            for (int dx = 0; dx < 2; dx++) {
                const int ix = x0 + dx;
                const int iy = y0 + dy;
                const float w = (dx ? wx1 : 1.f - wx1) * (dy ? wy1 : 1.f - wy1);
                const bool valid = (ix >= 0) & (ix < Wsz) & (iy >= 0) & (iy < Hs);
                const int cx = min(max(ix, 0), Wsz - 1);
                const int cy = min(max(iy, 0), Hs - 1);
                si[wslot][lane][dy * 2 + dx]  = vb + (cy * Wsz + cx) * C_;
                swt[wslot][lane][dy * 2 + dx] = valid ? (w * aw) : 0.f;
            }
        }
    }
    __syncwarp();

    const int c = lane >> 3;      // corner 0..3
    const int g = lane & 7;       // channel group (4 ch)
    float4 acc = make_float4(0.f, 0.f, 0.f, 0.f);
    #pragma unroll
    for (int p = 0; p < NPT; p++) {
        const int   idx = si[wslot][p][c];
        const float w   = swt[wslot][p][c];
        const float4 val = __ldg((const float4*)(v + idx) + g);
        acc.x = fmaf(w, val.x, acc.x);
        acc.y = fmaf(w, val.y, acc.y);
        acc.z = fmaf(w, val.z, acc.z);
        acc.w = fmaf(w, val.w, acc.w);
    }
    #pragma unroll
    for (int o = 8; o <= 16; o <<= 1) {
        acc.x += __shfl_xor_sync(0xFFFFFFFFu, acc.x, o);
        acc.y += __shfl_xor_sync(0xFFFFFFFFu, acc.y, o);
        acc.z += __shfl_xor_sync(0xFFFFFFFFu, acc.z, o);
        acc.w += __shfl_xor_sync(0xFFFFFFFFu, acc.w, o);
    }
    if (c == 0) {
        uint2 hp, lp;
        split4(acc, hp, lp);
        const size_t eo = ((size_t)bq * C_ + head * HD_ + g * 4) >> 2;
        ((uint2*)out_hi)[eo] = hp;
        ((uint2*)out_lo)[eo] = lp;
    }
}

// ---------------- launch ----------------
extern "C" void kernel_launch(void* const* d_in, const int* in_sizes, int n_in,
                              void* d_out, int out_size)
{
    const float* query = (const float*)d_in[0];
    const float* refp  = (const float*)d_in[1];
    const float* value = (const float*)d_in[2];
    const float* Wv    = (const float*)d_in[3];
    const float* bv    = (const float*)d_in[4];
    const float* Woff  = (const float*)d_in[5];
    const float* boff  = (const float*)d_in[6];
    const float* Wa    = (const float*)d_in[7];
    const float* ba    = (const float*)d_in[8];
    const float* Wo    = (const float*)d_in[9];
    const float* bo    = (const float*)d_in[10];
    float* out = (float*)d_out;

    float *p_v, *p_oa, *p_bfa;
    __nv_bfloat16 *p_vh, *p_vl, *p_qh, *p_ql, *p_th, *p_tl;
    __nv_bfloat16 *p_Wvh, *p_Wvl, *p_Wfah, *p_Wfal, *p_Woh, *p_Wol;
    cudaGetSymbolAddress((void**)&p_v,    g_v);
    cudaGetSymbolAddress((void**)&p_oa,   g_oa);
    cudaGetSymbolAddress((void**)&p_bfa,  g_bfa);
    cudaGetSymbolAddress((void**)&p_vh,   g_val_hi);
    cudaGetSymbolAddress((void**)&p_vl,   g_val_lo);
    cudaGetSymbolAddress((void**)&p_qh,   g_q_hi);
    cudaGetSymbolAddress((void**)&p_ql,   g_q_lo);
    cudaGetSymbolAddress((void**)&p_th,   g_tmp_hi);
    cudaGetSymbolAddress((void**)&p_tl,   g_tmp_lo);
    cudaGetSymbolAddress((void**)&p_Wvh,  g_Wv_hi);
    cudaGetSymbolAddress((void**)&p_Wvl,  g_Wv_lo);
    cudaGetSymbolAddress((void**)&p_Wfah, g_Wfa_hi);
    cudaGetSymbolAddress((void**)&p_Wfal, g_Wfa_lo);
    cudaGetSymbolAddress((void**)&p_Woh,  g_Wo_hi);
    cudaGetSymbolAddress((void**)&p_Wol,  g_Wo_lo);

    static bool attr_set = false;
    if (!attr_set) {
        cudaFuncSetAttribute(gemm_bf, cudaFuncAttributeMaxDynamicSharedMemorySize, GSMEM);
        attr_set = true;
    }

    const dim3 blk(256);

    // 1) all conversions in one launch
    cvt_all<<<(CN6 + 255) / 256, blk>>>(value, query, Wv, Woff, Wa, Wo, boff, ba);
    // 2) v = value @ Wv^T + bv        (N=256)
    gemm_bf<<<dim3(2, 84), blk, GSMEM>>>(p_vh, p_vl, p_Wvh, p_Wvl, bv, p_v, 256);
    // 3) [off|attn] = query @ Wfa^T + bfa  (N=288)
    gemm_bf<<<dim3(3, 84), blk, GSMEM>>>(p_qh, p_ql, p_Wfah, p_Wfal, p_bfa, p_oa, NFA);
    // 4) fused softmax + bilinear + gather (writes split bf16 tmp)
    msda_sample<<<(MR * HEADS_) / 8, blk>>>(p_v, refp, p_oa, p_th, p_tl);
    // 5) out = tmp @ Wo^T + bo        (N=256)
    gemm_bf<<<dim3(2, 84), blk, GSMEM>>>(p_th, p_tl, p_Woh, p_Wol, bo, out, 256);
}

// round 8
// speedup vs baseline: 1.5730x; 1.1337x over previous
#include <cuda_runtime.h>
#include <cuda_bf16.h>
#include <stdint.h>
#include <math.h>

// ---------------- problem constants ----------------
#define B_    2
#define NQ_   5376
#define NV_   5376
#define C_    256
#define HEADS_ 8
#define HD_   32
#define NPT   12
#define KD    256
#define MR    10752       // B*NQ
#define NFA   288         // 192 (off) + 96 (attn) fused

// ---------------- scratch ----------------
__device__ float g_v[(size_t)MR * C_];
__device__ float g_oa[(size_t)MR * NFA];
__device__ float g_bfa[NFA];
__device__ __nv_bfloat16 g_val_hi[(size_t)MR * C_];
__device__ __nv_bfloat16 g_val_lo[(size_t)MR * C_];
__device__ __nv_bfloat16 g_q_hi[(size_t)MR * C_];
__device__ __nv_bfloat16 g_q_lo[(size_t)MR * C_];
__device__ __nv_bfloat16 g_tmp_hi[(size_t)MR * C_];
__device__ __nv_bfloat16 g_tmp_lo[(size_t)MR * C_];
__device__ __nv_bfloat16 g_Wv_hi[256 * 256],  g_Wv_lo[256 * 256];
__device__ __nv_bfloat16 g_Wfa_hi[NFA * 256], g_Wfa_lo[NFA * 256];
__device__ __nv_bfloat16 g_Wo_hi[256 * 256],  g_Wo_lo[256 * 256];

// ---------------- helpers ----------------
__device__ __forceinline__ uint32_t smem_u32(const void* p) {
    uint32_t a;
    asm("{ .reg .u64 t; cvta.to.shared.u64 t, %1; cvt.u32.u64 %0, t; }" : "=r"(a) : "l"(p));
    return a;
}
__device__ __forceinline__ uint32_t pack_bf2(float x, float y) {
    uint32_t r;
    asm("cvt.rn.bf16x2.f32 %0, %1, %2;" : "=r"(r) : "f"(y), "f"(x));
    return r;
}
__device__ __forceinline__ void split4(float4 v, uint2& hp, uint2& lp) {
    const uint32_t h01 = pack_bf2(v.x, v.y);
    const uint32_t h23 = pack_bf2(v.z, v.w);
    const float hx = __uint_as_float(h01 << 16);
    const float hy = __uint_as_float(h01 & 0xFFFF0000u);
    const float hz = __uint_as_float(h23 << 16);
    const float hw = __uint_as_float(h23 & 0xFFFF0000u);
    hp = make_uint2(h01, h23);
    lp = make_uint2(pack_bf2(v.x - hx, v.y - hy), pack_bf2(v.z - hz, v.w - hw));
}

#define LDM4(r, addr) \
    asm volatile("ldmatrix.sync.aligned.m8n8.x4.shared.b16 {%0,%1,%2,%3}, [%4];" \
        : "=r"((r)[0]), "=r"((r)[1]), "=r"((r)[2]), "=r"((r)[3]) : "r"(addr))

#define MMA_BF16(d, a, b0, b1) \
    asm volatile("mma.sync.aligned.m16n8k16.row.col.f32.bf16.bf16.f32 " \
        "{%0,%1,%2,%3}, {%4,%5,%6,%7}, {%8,%9}, {%0,%1,%2,%3};" \
        : "+f"((d)[0]), "+f"((d)[1]), "+f"((d)[2]), "+f"((d)[3]) \
        : "r"((a)[0]), "r"((a)[1]), "r"((a)[2]), "r"((a)[3]), "r"(b0), "r"(b1))

#define CPA(dst, src, sz) \
    asm volatile("cp.async.cg.shared.global [%0], [%1], 16, %2;" \
        :: "r"(dst), "l"(src), "r"(sz) : "memory")
#define CPCOMMIT() asm volatile("cp.async.commit_group;" ::: "memory")
#define CPWAIT(n)  asm volatile("cp.async.wait_group %0;" :: "n"(n) : "memory")

// ---------------- fused convert ----------------
#define CN0 (MR * C_ / 4)
#define CN1 (CN0 + MR * C_ / 4)
#define CN2 (CN1 + 256 * 256 / 4)
#define CN3 (CN2 + 192 * 256 / 4)
#define CN4 (CN3 + 96 * 256 / 4)
#define CN5 (CN4 + 256 * 256 / 4)
#define CN6 (CN5 + 72)

__global__ __launch_bounds__(256)
void cvt_all(const float* __restrict__ value, const float* __restrict__ query,
             const float* __restrict__ Wv, const float* __restrict__ Woff,
             const float* __restrict__ Wa, const float* __restrict__ Wo,
             const float* __restrict__ boff, const float* __restrict__ ba)
{
    const int i = blockIdx.x * blockDim.x + threadIdx.x;
    if (i >= CN6) return;

    const float4* src;
    __nv_bfloat16 *hi, *lo;
    int j;
    if (i < CN0)      { src = (const float4*)value; hi = g_val_hi; lo = g_val_lo; j = i; }
    else if (i < CN1) { src = (const float4*)query; hi = g_q_hi;   lo = g_q_lo;   j = i - CN0; }
    else if (i < CN2) { src = (const float4*)Wv;    hi = g_Wv_hi;  lo = g_Wv_lo;  j = i - CN1; }
    else if (i < CN3) { src = (const float4*)Woff;  hi = g_Wfa_hi; lo = g_Wfa_lo; j = i - CN2; }
    else if (i < CN4) { src = (const float4*)Wa;    hi = g_Wfa_hi + 192 * 256;
                        lo = g_Wfa_lo + 192 * 256;  j = i - CN3; }
    else if (i < CN5) { src = (const float4*)Wo;    hi = g_Wo_hi;  lo = g_Wo_lo;  j = i - CN4; }
    else {
        const int k = i - CN5;
        ((float4*)g_bfa)[k] = (k < 48) ? ((const float4*)boff)[k]
                                       : ((const float4*)ba)[k - 48];
        return;
    }
    uint2 hp, lp;
    split4(src[j], hp, lp);
    ((uint2*)hi)[j] = hp;
    ((uint2*)lo)[j] = lp;
}

// ---------------- split-bf16 mma.sync GEMM core ----------------
#define S_ 40
#define STG_B (128 * S_ * 2)           // 10240 B per buffer
#define STAGE_B (4 * STG_B)            // 40960 B per stage
#define GSMEM (2 * STAGE_B)            // 81920 B

__device__ __forceinline__ void gemm_core(
    const __nv_bfloat16* __restrict__ Ahi, const __nv_bfloat16* __restrict__ Alo,
    const __nv_bfloat16* __restrict__ Whi, const __nv_bfloat16* __restrict__ Wlo,
    const float* __restrict__ bias, float* __restrict__ Cc,
    int Ntrue, int bm, int bn, char* smem)
{
    const int tid  = threadIdx.x;
    const int wid  = tid >> 5;
    const int lane = tid & 31;
    const int wm   = wid >> 1;
    const int wn   = wid & 1;
    const int wrows = Ntrue - bn;

    const uint32_t sb = smem_u32(smem);

    float acc[2][8][4];
    #pragma unroll
    for (int i = 0; i < 2; i++)
        #pragma unroll
        for (int j = 0; j < 8; j++)
            #pragma unroll
            for (int k = 0; k < 4; k++) acc[i][j][k] = 0.f;

    auto prefetch = [&](int ch, int stg) {
        const int k0 = ch * 32;
        const uint32_t base = sb + stg * STAGE_B;
        #pragma unroll
        for (int i = 0; i < 2; i++) {
            const int f   = tid + i * 256;
            const int row = f >> 2;
            const int col = (f & 3) << 3;
            const uint32_t sdst = (row * S_ + col) * 2;
            const size_t aoff = (size_t)(bm + row) * KD + k0 + col;
            CPA(base + 0 * STG_B + sdst, Ahi + aoff, 16);
            CPA(base + 1 * STG_B + sdst, Alo + aoff, 16);
            const int valid = (row < wrows) ? 16 : 0;
            const int wr    = (row < wrows) ? row : 0;
            const size_t woff = (size_t)(bn + wr) * KD + k0 + col;
            CPA(base + 2 * STG_B + sdst, Whi + woff, valid);
            CPA(base + 3 * STG_B + sdst, Wlo + woff, valid);
        }
        CPCOMMIT();
    };

    const int a_row = lane & 15;
    const int a_kc  = (lane & 16) ? 8 : 0;
    const int b_row = (lane & 7) + ((lane & 16) ? 8 : 0);
    const int b_kc  = (lane & 8) ? 8 : 0;

    prefetch(0, 0);

    #pragma unroll 1
    for (int ch = 0; ch < 8; ch++) {
        const int cur = ch & 1;
        if (ch < 7) {
            prefetch(ch + 1, cur ^ 1);
            CPWAIT(1);
        } else {
            CPWAIT(0);
        }
        __syncthreads();

        const uint32_t base = sb + cur * STAGE_B;
        const uint32_t uAhi = base;
        const uint32_t uAlo = base + STG_B;
        const uint32_t uWhi = base + 2 * STG_B;
        const uint32_t uWlo = base + 3 * STG_B;

        #pragma unroll
        for (int ks = 0; ks < 2; ks++) {
            const int kb = ks * 16;
            uint32_t ah[2][4], al[2][4];
            #pragma unroll
            for (int mf = 0; mf < 2; mf++) {
                const int e = (wm * 32 + mf * 16 + a_row) * S_ + kb + a_kc;
                LDM4(ah[mf], uAhi + e * 2);
                LDM4(al[mf], uAlo + e * 2);
            }
            #pragma unroll
            for (int nf = 0; nf < 4; nf++) {
                uint32_t bh[4], bl[4];
                const int e = (wn * 64 + nf * 16 + b_row) * S_ + kb + b_kc;
                LDM4(bh, uWhi + e * 2);
                LDM4(bl, uWlo + e * 2);
                #pragma unroll
                for (int mf = 0; mf < 2; mf++) {
                    MMA_BF16(acc[mf][nf * 2 + 0], ah[mf], bh[0], bh[1]);
                    MMA_BF16(acc[mf][nf * 2 + 1], ah[mf], bh[2], bh[3]);
                    MMA_BF16(acc[mf][nf * 2 + 0], ah[mf], bl[0], bl[1]);
                    MMA_BF16(acc[mf][nf * 2 + 1], ah[mf], bl[2], bl[3]);
                    MMA_BF16(acc[mf][nf * 2 + 0], al[mf], bh[0], bh[1]);
                    MMA_BF16(acc[mf][nf * 2 + 1], al[mf], bh[2], bh[3]);
                }
            }
        }
        __syncthreads();
    }

    const int grp  = lane >> 2;
    const int tid4 = lane & 3;
    #pragma unroll
    for (int mf = 0; mf < 2; mf++) {
        const int row0 = bm + wm * 32 + mf * 16 + grp;
        #pragma unroll
        for (int nf = 0; nf < 8; nf++) {
            const int gn = bn + wn * 64 + nf * 8 + tid4 * 2;
            if (gn < Ntrue) {
                const float bb0 = bias[gn];
                const float bb1 = bias[gn + 1];
                *(float2*)&Cc[(size_t)row0 * Ntrue + gn] =
                    make_float2(acc[mf][nf][0] + bb0, acc[mf][nf][1] + bb1);
                *(float2*)&Cc[(size_t)(row0 + 8) * Ntrue + gn] =
                    make_float2(acc[mf][nf][2] + bb0, acc[mf][nf][3] + bb1);
            }
        }
    }
}

// fused GEMM1+GEMM2: grid.x in [0,5): x<2 -> value-proj (N=256), else off/attn (N=288)
__global__ __launch_bounds__(256, 2)
void gemm_fused12(const __nv_bfloat16* __restrict__ vh, const __nv_bfloat16* __restrict__ vl,
                  const __nv_bfloat16* __restrict__ qh, const __nv_bfloat16* __restrict__ ql,
                  const __nv_bfloat16* __restrict__ Wvh, const __nv_bfloat16* __restrict__ Wvl,
                  const __nv_bfloat16* __restrict__ Wfah, const __nv_bfloat16* __restrict__ Wfal,
                  const float* __restrict__ bv, const float* __restrict__ bfa,
                  float* __restrict__ outv, float* __restrict__ outoa)
{
    extern __shared__ __align__(16) char smem[];
    const int bm = blockIdx.y * 128;
    if (blockIdx.x < 2) {
        gemm_core(vh, vl, Wvh, Wvl, bv, outv, 256, bm, blockIdx.x * 128, smem);
    } else {
        gemm_core(qh, ql, Wfah, Wfal, bfa, outoa, NFA, bm, (blockIdx.x - 2) * 128, smem);
    }
}

__global__ __launch_bounds__(256, 2)
void gemm_bf(const __nv_bfloat16* __restrict__ Ahi, const __nv_bfloat16* __restrict__ Alo,
             const __nv_bfloat16* __restrict__ Whi, const __nv_bfloat16* __restrict__ Wlo,
             const float* __restrict__ bias, float* __restrict__ Cc, int Ntrue)
{
    extern __shared__ __align__(16) char smem[];
    gemm_core(Ahi, Alo, Whi, Wlo, bias, Cc, Ntrue, blockIdx.y * 128, blockIdx.x * 128, smem);
}

// ---------------- fused sampling ----------------
__global__ __launch_bounds__(256)
void msda_sample(const float* __restrict__ v, const float* __restrict__ ref,
                 const float* __restrict__ oa,
                 __nv_bfloat16* __restrict__ out_hi, __nv_bfloat16* __restrict__ out_lo)
{
    __shared__ int2 spk[8][NPT][4];     // (idx, weight-bits) per corner
    const int wslot = threadIdx.x >> 5;
    const int lane  = threadIdx.x & 31;
    const int warp  = blockIdx.x * 8 + wslot;
    const int head  = warp & 7;
    const int bq    = warp >> 3;
    const int b     = bq / NQ_;

    float lg = -1e30f;
    if (lane < NPT) lg = oa[(size_t)bq * NFA + 192 + head * NPT + lane];
    float mx = lg;
    #pragma unroll
    for (int o = 16; o; o >>= 1) mx = fmaxf(mx, __shfl_xor_sync(0xFFFFFFFFu, mx, o));
    float e = (lane < NPT) ? __expf(lg - mx) : 0.f;
    float s = e;
    #pragma unroll
    for (int o = 16; o; o >>= 1) s += __shfl_xor_sync(0xFFFFFFFFu, s, o);

    if (lane < NPT) {
        const float aw  = e / s;
        const int lvl   = lane >> 2;
        const int Hs    = 64 >> lvl;
        const int Wsz   = Hs;
        const int start = (lvl == 0) ? 0 : (lvl == 1) ? 4096 : 5120;
        const float rx = ref[(size_t)bq * 2 + 0];
        const float ry = ref[(size_t)bq * 2 + 1];
        const float ox = oa[(size_t)bq * NFA + head * 24 + lane * 2 + 0];
        const float oy = oa[(size_t)bq * NFA + head * 24 + lane * 2 + 1];
        const float lx = fminf(fmaxf(rx + ox, 0.f), 1.f);
        const float ly = fminf(fmaxf(ry + oy, 0.f), 1.f);
        const float x = lx * (float)Wsz - 0.5f;
        const float y = ly * (float)Hs - 0.5f;
        const float x0f = floorf(x);
        const float y0f = floorf(y);
        const float wx1 = x - x0f;
        const float wy1 = y - y0f;
        const int x0 = (int)x0f;
        const int y0 = (int)y0f;
        const int vb = (b * NV_ + start) * C_ + head * HD_;
        #pragma unroll
        for (int dy = 0; dy < 2; dy++) {
            #pragma unroll
            for (int dx = 0; dx < 2; dx++) {
                const int ix = x0 + dx;
                const int iy = y0 + dy;
                const float w = (dx ? wx1 : 1.f - wx1) * (dy ? wy1 : 1.f - wy1);
                const bool valid = (ix >= 0) & (ix < Wsz) & (iy >= 0) & (iy < Hs);
                const int cx = min(max(ix, 0), Wsz - 1);
                const int cy = min(max(iy, 0), Hs - 1);
                spk[wslot][lane][dy * 2 + dx] =
                    make_int2(vb + (cy * Wsz + cx) * C_,
                              __float_as_int(valid ? (w * aw) : 0.f));
            }
        }
    }
    __syncwarp();

    const int c = lane >> 3;
    const int g = lane & 7;
    float4 acc = make_float4(0.f, 0.f, 0.f, 0.f);
    #pragma unroll
    for (int p = 0; p < NPT; p++) {
        const int2 iw = spk[wslot][p][c];
        const float w = __int_as_float(iw.y);
        const float4 val = __ldg((const float4*)(v + iw.x) + g);
        acc.x = fmaf(w, val.x, acc.x);
        acc.y = fmaf(w, val.y, acc.y);
        acc.z = fmaf(w, val.z, acc.z);
        acc.w = fmaf(w, val.w, acc.w);
    }
    #pragma unroll
    for (int o = 8; o <= 16; o <<= 1) {
        acc.x += __shfl_xor_sync(0xFFFFFFFFu, acc.x, o);
        acc.y += __shfl_xor_sync(0xFFFFFFFFu, acc.y, o);
        acc.z += __shfl_xor_sync(0xFFFFFFFFu, acc.z, o);
        acc.w += __shfl_xor_sync(0xFFFFFFFFu, acc.w, o);
    }
    if (c == 0) {
        uint2 hp, lp;
        split4(acc, hp, lp);
        const size_t eo = ((size_t)bq * C_ + head * HD_ + g * 4) >> 2;
        ((uint2*)out_hi)[eo] = hp;
        ((uint2*)out_lo)[eo] = lp;
    }
}

// ---------------- launch ----------------
extern "C" void kernel_launch(void* const* d_in, const int* in_sizes, int n_in,
                              void* d_out, int out_size)
{
    const float* query = (const float*)d_in[0];
    const float* refp  = (const float*)d_in[1];
    const float* value = (const float*)d_in[2];
    const float* Wv    = (const float*)d_in[3];
    const float* bv    = (const float*)d_in[4];
    const float* Woff  = (const float*)d_in[5];
    const float* boff  = (const float*)d_in[6];
    const float* Wa    = (const float*)d_in[7];
    const float* ba    = (const float*)d_in[8];
    const float* Wo    = (const float*)d_in[9];
    const float* bo    = (const float*)d_in[10];
    float* out = (float*)d_out;

    float *p_v, *p_oa, *p_bfa;
    __nv_bfloat16 *p_vh, *p_vl, *p_qh, *p_ql, *p_th, *p_tl;
    __nv_bfloat16 *p_Wvh, *p_Wvl, *p_Wfah, *p_Wfal, *p_Woh, *p_Wol;
    cudaGetSymbolAddress((void**)&p_v,    g_v);
    cudaGetSymbolAddress((void**)&p_oa,   g_oa);
    cudaGetSymbolAddress((void**)&p_bfa,  g_bfa);
    cudaGetSymbolAddress((void**)&p_vh,   g_val_hi);
    cudaGetSymbolAddress((void**)&p_vl,   g_val_lo);
    cudaGetSymbolAddress((void**)&p_qh,   g_q_hi);
    cudaGetSymbolAddress((void**)&p_ql,   g_q_lo);
    cudaGetSymbolAddress((void**)&p_th,   g_tmp_hi);
    cudaGetSymbolAddress((void**)&p_tl,   g_tmp_lo);
    cudaGetSymbolAddress((void**)&p_Wvh,  g_Wv_hi);
    cudaGetSymbolAddress((void**)&p_Wvl,  g_Wv_lo);
    cudaGetSymbolAddress((void**)&p_Wfah, g_Wfa_hi);
    cudaGetSymbolAddress((void**)&p_Wfal, g_Wfa_lo);
    cudaGetSymbolAddress((void**)&p_Woh,  g_Wo_hi);
    cudaGetSymbolAddress((void**)&p_Wol,  g_Wo_lo);

    static bool attr_set = false;
    if (!attr_set) {
        cudaFuncSetAttribute(gemm_fused12, cudaFuncAttributeMaxDynamicSharedMemorySize, GSMEM);
        cudaFuncSetAttribute(gemm_fused12, cudaFuncAttributePreferredSharedMemoryCarveout, 100);
        cudaFuncSetAttribute(gemm_bf, cudaFuncAttributeMaxDynamicSharedMemorySize, GSMEM);
        cudaFuncSetAttribute(gemm_bf, cudaFuncAttributePreferredSharedMemoryCarveout, 100);
        attr_set = true;
    }

    const dim3 blk(256);

    // 1) all conversions in one launch
    cvt_all<<<(CN6 + 255) / 256, blk>>>(value, query, Wv, Woff, Wa, Wo, boff, ba);
    // 2+3) fused: v = value@Wv^T+bv  AND  [off|attn] = query@Wfa^T+bfa
    gemm_fused12<<<dim3(5, 84), blk, GSMEM>>>(p_vh, p_vl, p_qh, p_ql,
                                              p_Wvh, p_Wvl, p_Wfah, p_Wfal,
                                              bv, p_bfa, p_v, p_oa);
    // 4) fused softmax + bilinear + gather
    msda_sample<<<(MR * HEADS_) / 8, blk>>>(p_v, refp, p_oa, p_th, p_tl);
    // 5) out = tmp @ Wo^T + bo
    gemm_bf<<<dim3(2, 84), blk, GSMEM>>>(p_th, p_tl, p_Woh, p_Wol, bo, out, 256);
}

// round 9
// speedup vs baseline: 1.6041x; 1.0198x over previous
#include <cuda_runtime.h>
#include <cuda_bf16.h>
#include <stdint.h>
#include <math.h>

// ---------------- problem constants ----------------
#define B_    2
#define NQ_   5376
#define NV_   5376
#define C_    256
#define HEADS_ 8
#define HD_   32
#define NPT   12
#define KD    256
#define MR    10752       // B*NQ
#define NFA   288         // 192 (off) + 96 (attn) fused

// ---------------- scratch ----------------
__device__ float g_v[(size_t)MR * C_];
__device__ float g_oa[(size_t)MR * NFA];
__device__ float g_bfa[NFA];
__device__ __nv_bfloat16 g_val_hi[(size_t)MR * C_];
__device__ __nv_bfloat16 g_val_lo[(size_t)MR * C_];
__device__ __nv_bfloat16 g_q_hi[(size_t)MR * C_];
__device__ __nv_bfloat16 g_q_lo[(size_t)MR * C_];
__device__ __nv_bfloat16 g_tmp_hi[(size_t)MR * C_];
__device__ __nv_bfloat16 g_tmp_lo[(size_t)MR * C_];
__device__ __nv_bfloat16 g_Wv_hi[256 * 256],  g_Wv_lo[256 * 256];
__device__ __nv_bfloat16 g_Wfa_hi[NFA * 256], g_Wfa_lo[NFA * 256];
__device__ __nv_bfloat16 g_Wo_hi[256 * 256],  g_Wo_lo[256 * 256];

// ---------------- helpers ----------------
__device__ __forceinline__ uint32_t smem_u32(const void* p) {
    uint32_t a;
    asm("{ .reg .u64 t; cvta.to.shared.u64 t, %1; cvt.u32.u64 %0, t; }" : "=r"(a) : "l"(p));
    return a;
}
__device__ __forceinline__ uint32_t pack_bf2(float x, float y) {
    uint32_t r;
    asm("cvt.rn.bf16x2.f32 %0, %1, %2;" : "=r"(r) : "f"(y), "f"(x));
    return r;
}
__device__ __forceinline__ void split4(float4 v, uint2& hp, uint2& lp) {
    const uint32_t h01 = pack_bf2(v.x, v.y);
    const uint32_t h23 = pack_bf2(v.z, v.w);
    const float hx = __uint_as_float(h01 << 16);
    const float hy = __uint_as_float(h01 & 0xFFFF0000u);
    const float hz = __uint_as_float(h23 << 16);
    const float hw = __uint_as_float(h23 & 0xFFFF0000u);
    hp = make_uint2(h01, h23);
    lp = make_uint2(pack_bf2(v.x - hx, v.y - hy), pack_bf2(v.z - hz, v.w - hw));
}

#define LDM4(r, addr) \
    asm volatile("ldmatrix.sync.aligned.m8n8.x4.shared.b16 {%0,%1,%2,%3}, [%4];" \
        : "=r"((r)[0]), "=r"((r)[1]), "=r"((r)[2]), "=r"((r)[3]) : "r"(addr))

#define MMA_BF16(d, a, b0, b1) \
    asm volatile("mma.sync.aligned.m16n8k16.row.col.f32.bf16.bf16.f32 " \
        "{%0,%1,%2,%3}, {%4,%5,%6,%7}, {%8,%9}, {%0,%1,%2,%3};" \
        : "+f"((d)[0]), "+f"((d)[1]), "+f"((d)[2]), "+f"((d)[3]) \
        : "r"((a)[0]), "r"((a)[1]), "r"((a)[2]), "r"((a)[3]), "r"(b0), "r"(b1))

#define CPA(dst, src, sz) \
    asm volatile("cp.async.cg.shared.global [%0], [%1], 16, %2;" \
        :: "r"(dst), "l"(src), "r"(sz) : "memory")
#define CPCOMMIT() asm volatile("cp.async.commit_group;" ::: "memory")
#define CPWAIT(n)  asm volatile("cp.async.wait_group %0;" :: "n"(n) : "memory")

// ---------------- fused convert ----------------
#define CN0 (MR * C_ / 4)
#define CN1 (CN0 + MR * C_ / 4)
#define CN2 (CN1 + 256 * 256 / 4)
#define CN3 (CN2 + 192 * 256 / 4)
#define CN4 (CN3 + 96 * 256 / 4)
#define CN5 (CN4 + 256 * 256 / 4)
#define CN6 (CN5 + 72)

__global__ __launch_bounds__(256)
void cvt_all(const float* __restrict__ value, const float* __restrict__ query,
             const float* __restrict__ Wv, const float* __restrict__ Woff,
             const float* __restrict__ Wa, const float* __restrict__ Wo,
             const float* __restrict__ boff, const float* __restrict__ ba)
{
    const int i = blockIdx.x * blockDim.x + threadIdx.x;
    if (i >= CN6) return;

    const float4* src;
    __nv_bfloat16 *hi, *lo;
    int j;
    if (i < CN0)      { src = (const float4*)value; hi = g_val_hi; lo = g_val_lo; j = i; }
    else if (i < CN1) { src = (const float4*)query; hi = g_q_hi;   lo = g_q_lo;   j = i - CN0; }
    else if (i < CN2) { src = (const float4*)Wv;    hi = g_Wv_hi;  lo = g_Wv_lo;  j = i - CN1; }
    else if (i < CN3) { src = (const float4*)Woff;  hi = g_Wfa_hi; lo = g_Wfa_lo; j = i - CN2; }
    else if (i < CN4) { src = (const float4*)Wa;    hi = g_Wfa_hi + 192 * 256;
                        lo = g_Wfa_lo + 192 * 256;  j = i - CN3; }
    else if (i < CN5) { src = (const float4*)Wo;    hi = g_Wo_hi;  lo = g_Wo_lo;  j = i - CN4; }
    else {
        const int k = i - CN5;
        ((float4*)g_bfa)[k] = (k < 48) ? ((const float4*)boff)[k]
                                       : ((const float4*)ba)[k - 48];
        return;
    }
    uint2 hp, lp;
    split4(src[j], hp, lp);
    ((uint2*)hi)[j] = hp;
    ((uint2*)lo)[j] = lp;
}

// ---------------- split-bf16 mma.sync GEMM core ----------------
// BM=64, BN=128, BK=32, 256 threads, 8 warps (2m x 4n), warp tile 32x32
#define S_ 40
#define STG_A (64 * S_ * 2)            // 5120 B  (A hi or lo)
#define STG_W (128 * S_ * 2)           // 10240 B (W hi or lo)
#define STAGE_B (2 * STG_A + 2 * STG_W)  // 30720 B per stage
#define GSMEM (2 * STAGE_B)              // 61440 B

__device__ __forceinline__ void gemm_core(
    const __nv_bfloat16* __restrict__ Ahi, const __nv_bfloat16* __restrict__ Alo,
    const __nv_bfloat16* __restrict__ Whi, const __nv_bfloat16* __restrict__ Wlo,
    const float* __restrict__ bias, float* __restrict__ Cc,
    int Ntrue, int bm, int bn, char* smem)
{
    const int tid  = threadIdx.x;
    const int wid  = tid >> 5;
    const int lane = tid & 31;
    const int wm   = wid >> 2;          // 0..1 : 32-row strip
    const int wn   = wid & 3;           // 0..3 : 32-col strip
    const int wrows = Ntrue - bn;

    const uint32_t sb = smem_u32(smem);

    float acc[2][4][4];
    #pragma unroll
    for (int i = 0; i < 2; i++)
        #pragma unroll
        for (int j = 0; j < 4; j++)
            #pragma unroll
            for (int k = 0; k < 4; k++) acc[i][j][k] = 0.f;

    auto prefetch = [&](int ch, int stg) {
        const int k0 = ch * 32;
        const uint32_t base = sb + stg * STAGE_B;
        // A: 64 rows x 32 k = 256 x 16B chunks, 1 per thread
        {
            const int row = tid >> 2;             // 0..63
            const int col = (tid & 3) << 3;       // 0,8,16,24
            const uint32_t sdst = (row * S_ + col) * 2;
            const size_t aoff = (size_t)(bm + row) * KD + k0 + col;
            CPA(base + 0 * STG_A + sdst, Ahi + aoff, 16);
            CPA(base + 1 * STG_A + sdst, Alo + aoff, 16);
        }
        // W: 128 rows x 32 k = 512 x 16B chunks, 2 per thread
        #pragma unroll
        for (int i = 0; i < 2; i++) {
            const int f   = tid + i * 256;
            const int row = f >> 2;               // 0..127
            const int col = (f & 3) << 3;
            const uint32_t sdst = (row * S_ + col) * 2;
            const int valid = (row < wrows) ? 16 : 0;
            const int wr    = (row < wrows) ? row : 0;
            const size_t woff = (size_t)(bn + wr) * KD + k0 + col;
            CPA(base + 2 * STG_A + 0 * STG_W + sdst, Whi + woff, valid);
            CPA(base + 2 * STG_A + 1 * STG_W + sdst, Wlo + woff, valid);
        }
        CPCOMMIT();
    };

    const int a_row = lane & 15;
    const int a_kc  = (lane & 16) ? 8 : 0;
    const int b_row = (lane & 7) + ((lane & 16) ? 8 : 0);
    const int b_kc  = (lane & 8) ? 8 : 0;

    prefetch(0, 0);

    #pragma unroll 1
    for (int ch = 0; ch < 8; ch++) {
        const int cur = ch & 1;
        if (ch < 7) {
            prefetch(ch + 1, cur ^ 1);
            CPWAIT(1);
        } else {
            CPWAIT(0);
        }
        __syncthreads();

        const uint32_t base = sb + cur * STAGE_B;
        const uint32_t uAhi = base;
        const uint32_t uAlo = base + STG_A;
        const uint32_t uWhi = base + 2 * STG_A;
        const uint32_t uWlo = base + 2 * STG_A + STG_W;

        #pragma unroll
        for (int ks = 0; ks < 2; ks++) {
            const int kb = ks * 16;
            uint32_t ah[2][4], al[2][4];
            #pragma unroll
            for (int mf = 0; mf < 2; mf++) {
                const int e = (wm * 32 + mf * 16 + a_row) * S_ + kb + a_kc;
                LDM4(ah[mf], uAhi + e * 2);
                LDM4(al[mf], uAlo + e * 2);
            }
            #pragma unroll
            for (int nf = 0; nf < 2; nf++) {
                uint32_t bh[4], bl[4];
                const int e = (wn * 32 + nf * 16 + b_row) * S_ + kb + b_kc;
                LDM4(bh, uWhi + e * 2);
                LDM4(bl, uWlo + e * 2);
                #pragma unroll
                for (int mf = 0; mf < 2; mf++) {
                    MMA_BF16(acc[mf][nf * 2 + 0], ah[mf], bh[0], bh[1]);
                    MMA_BF16(acc[mf][nf * 2 + 1], ah[mf], bh[2], bh[3]);
                    MMA_BF16(acc[mf][nf * 2 + 0], ah[mf], bl[0], bl[1]);
                    MMA_BF16(acc[mf][nf * 2 + 1], ah[mf], bl[2], bl[3]);
                    MMA_BF16(acc[mf][nf * 2 + 0], al[mf], bh[0], bh[1]);
                    MMA_BF16(acc[mf][nf * 2 + 1], al[mf], bh[2], bh[3]);
                }
            }
        }
        __syncthreads();
    }

    const int grp  = lane >> 2;
    const int tid4 = lane & 3;
    #pragma unroll
    for (int mf = 0; mf < 2; mf++) {
        const int row0 = bm + wm * 32 + mf * 16 + grp;
        #pragma unroll
        for (int j = 0; j < 4; j++) {
            const int gn = bn + wn * 32 + j * 8 + tid4 * 2;
            if (gn < Ntrue) {
                const float bb0 = bias[gn];
                const float bb1 = bias[gn + 1];
                *(float2*)&Cc[(size_t)row0 * Ntrue + gn] =
                    make_float2(acc[mf][j][0] + bb0, acc[mf][j][1] + bb1);
                *(float2*)&Cc[(size_t)(row0 + 8) * Ntrue + gn] =
                    make_float2(acc[mf][j][2] + bb0, acc[mf][j][3] + bb1);
            }
        }
    }
}

// fused GEMM1+GEMM2: grid.x in [0,5): x<2 -> value-proj (N=256), else off/attn (N=288)
__global__ __launch_bounds__(256, 3)
void gemm_fused12(const __nv_bfloat16* __restrict__ vh, const __nv_bfloat16* __restrict__ vl,
                  const __nv_bfloat16* __restrict__ qh, const __nv_bfloat16* __restrict__ ql,
                  const __nv_bfloat16* __restrict__ Wvh, const __nv_bfloat16* __restrict__ Wvl,
                  const __nv_bfloat16* __restrict__ Wfah, const __nv_bfloat16* __restrict__ Wfal,
                  const float* __restrict__ bv, const float* __restrict__ bfa,
                  float* __restrict__ outv, float* __restrict__ outoa)
{
    extern __shared__ __align__(16) char smem[];
    const int bm = blockIdx.y * 64;
    if (blockIdx.x < 2) {
        gemm_core(vh, vl, Wvh, Wvl, bv, outv, 256, bm, blockIdx.x * 128, smem);
    } else {
        gemm_core(qh, ql, Wfah, Wfal, bfa, outoa, NFA, bm, (blockIdx.x - 2) * 128, smem);
    }
}

__global__ __launch_bounds__(256, 3)
void gemm_bf(const __nv_bfloat16* __restrict__ Ahi, const __nv_bfloat16* __restrict__ Alo,
             const __nv_bfloat16* __restrict__ Whi, const __nv_bfloat16* __restrict__ Wlo,
             const float* __restrict__ bias, float* __restrict__ Cc, int Ntrue)
{
    extern __shared__ __align__(16) char smem[];
    gemm_core(Ahi, Alo, Whi, Wlo, bias, Cc, Ntrue, blockIdx.y * 64, blockIdx.x * 128, smem);
}

// ---------------- fused sampling ----------------
__global__ __launch_bounds__(256)
void msda_sample(const float* __restrict__ v, const float* __restrict__ ref,
                 const float* __restrict__ oa,
                 __nv_bfloat16* __restrict__ out_hi, __nv_bfloat16* __restrict__ out_lo)
{
    __shared__ int2 spk[8][NPT][4];
    const int wslot = threadIdx.x >> 5;
    const int lane  = threadIdx.x & 31;
    const int warp  = blockIdx.x * 8 + wslot;
    const int head  = warp & 7;
    const int bq    = warp >> 3;
    const int b     = bq / NQ_;

    float lg = -1e30f;
    if (lane < NPT) lg = oa[(size_t)bq * NFA + 192 + head * NPT + lane];
    float mx = lg;
    #pragma unroll
    for (int o = 16; o; o >>= 1) mx = fmaxf(mx, __shfl_xor_sync(0xFFFFFFFFu, mx, o));
    float e = (lane < NPT) ? __expf(lg - mx) : 0.f;
    float s = e;
    #pragma unroll
    for (int o = 16; o; o >>= 1) s += __shfl_xor_sync(0xFFFFFFFFu, s, o);

    if (lane < NPT) {
        const float aw  = e / s;
        const int lvl   = lane >> 2;
        const int Hs    = 64 >> lvl;
        const int Wsz   = Hs;
        const int start = (lvl == 0) ? 0 : (lvl == 1) ? 4096 : 5120;
        const float rx = ref[(size_t)bq * 2 + 0];
        const float ry = ref[(size_t)bq * 2 + 1];
        const float ox = oa[(size_t)bq * NFA + head * 24 + lane * 2 + 0];
        const float oy = oa[(size_t)bq * NFA + head * 24 + lane * 2 + 1];
        const float lx = fminf(fmaxf(rx + ox, 0.f), 1.f);
        const float ly = fminf(fmaxf(ry + oy, 0.f), 1.f);
        const float x = lx * (float)Wsz - 0.5f;
        const float y = ly * (float)Hs - 0.5f;
        const float x0f = floorf(x);
        const float y0f = floorf(y);
        const float wx1 = x - x0f;
        const float wy1 = y - y0f;
        const int x0 = (int)x0f;
        const int y0 = (int)y0f;
        const int vb = (b * NV_ + start) * C_ + head * HD_;
        #pragma unroll
        for (int dy = 0; dy < 2; dy++) {
            #pragma unroll
            for (int dx = 0; dx < 2; dx++) {
                const int ix = x0 + dx;
                const int iy = y0 + dy;
                const float w = (dx ? wx1 : 1.f - wx1) * (dy ? wy1 : 1.f - wy1);
                const bool valid = (ix >= 0) & (ix < Wsz) & (iy >= 0) & (iy < Hs);
                const int cx = min(max(ix, 0), Wsz - 1);
                const int cy = min(max(iy, 0), Hs - 1);
                spk[wslot][lane][dy * 2 + dx] =
                    make_int2(vb + (cy * Wsz + cx) * C_,
                              __float_as_int(valid ? (w * aw) : 0.f));
            }
        }
    }
    __syncwarp();

    const int c = lane >> 3;
    const int g = lane & 7;
    float4 acc = make_float4(0.f, 0.f, 0.f, 0.f);
    #pragma unroll
    for (int p = 0; p < NPT; p++) {
        const int2 iw = spk[wslot][p][c];
        const float w = __int_as_float(iw.y);
        const float4 val = __ldg((const float4*)(v + iw.x) + g);
        acc.x = fmaf(w, val.x, acc.x);
        acc.y = fmaf(w, val.y, acc.y);
        acc.z = fmaf(w, val.z, acc.z);
        acc.w = fmaf(w, val.w, acc.w);
    }
    #pragma unroll
    for (int o = 8; o <= 16; o <<= 1) {
        acc.x += __shfl_xor_sync(0xFFFFFFFFu, acc.x, o);
        acc.y += __shfl_xor_sync(0xFFFFFFFFu, acc.y, o);
        acc.z += __shfl_xor_sync(0xFFFFFFFFu, acc.z, o);
        acc.w += __shfl_xor_sync(0xFFFFFFFFu, acc.w, o);
    }
    if (c == 0) {
        uint2 hp, lp;
        split4(acc, hp, lp);
        const size_t eo = ((size_t)bq * C_ + head * HD_ + g * 4) >> 2;
        ((uint2*)out_hi)[eo] = hp;
        ((uint2*)out_lo)[eo] = lp;
    }
}

// ---------------- launch ----------------
extern "C" void kernel_launch(void* const* d_in, const int* in_sizes, int n_in,
                              void* d_out, int out_size)
{
    const float* query = (const float*)d_in[0];
    const float* refp  = (const float*)d_in[1];
    const float* value = (const float*)d_in[2];
    const float* Wv    = (const float*)d_in[3];
    const float* bv    = (const float*)d_in[4];
    const float* Woff  = (const float*)d_in[5];
    const float* boff  = (const float*)d_in[6];
    const float* Wa    = (const float*)d_in[7];
    const float* ba    = (const float*)d_in[8];
    const float* Wo    = (const float*)d_in[9];
    const float* bo    = (const float*)d_in[10];
    float* out = (float*)d_out;

    float *p_v, *p_oa, *p_bfa;
    __nv_bfloat16 *p_vh, *p_vl, *p_qh, *p_ql, *p_th, *p_tl;
    __nv_bfloat16 *p_Wvh, *p_Wvl, *p_Wfah, *p_Wfal, *p_Woh, *p_Wol;
    cudaGetSymbolAddress((void**)&p_v,    g_v);
    cudaGetSymbolAddress((void**)&p_oa,   g_oa);
    cudaGetSymbolAddress((void**)&p_bfa,  g_bfa);
    cudaGetSymbolAddress((void**)&p_vh,   g_val_hi);
    cudaGetSymbolAddress((void**)&p_vl,   g_val_lo);
    cudaGetSymbolAddress((void**)&p_qh,   g_q_hi);
    cudaGetSymbolAddress((void**)&p_ql,   g_q_lo);
    cudaGetSymbolAddress((void**)&p_th,   g_tmp_hi);
    cudaGetSymbolAddress((void**)&p_tl,   g_tmp_lo);
    cudaGetSymbolAddress((void**)&p_Wvh,  g_Wv_hi);
    cudaGetSymbolAddress((void**)&p_Wvl,  g_Wv_lo);
    cudaGetSymbolAddress((void**)&p_Wfah, g_Wfa_hi);
    cudaGetSymbolAddress((void**)&p_Wfal, g_Wfa_lo);
    cudaGetSymbolAddress((void**)&p_Woh,  g_Wo_hi);
    cudaGetSymbolAddress((void**)&p_Wol,  g_Wo_lo);

    static bool attr_set = false;
    if (!attr_set) {
        cudaFuncSetAttribute(gemm_fused12, cudaFuncAttributeMaxDynamicSharedMemorySize, GSMEM);
        cudaFuncSetAttribute(gemm_fused12, cudaFuncAttributePreferredSharedMemoryCarveout, 100);
        cudaFuncSetAttribute(gemm_bf, cudaFuncAttributeMaxDynamicSharedMemorySize, GSMEM);
        cudaFuncSetAttribute(gemm_bf, cudaFuncAttributePreferredSharedMemoryCarveout, 100);
        attr_set = true;
    }

    const dim3 blk(256);

    // 1) all conversions in one launch
    cvt_all<<<(CN6 + 255) / 256, blk>>>(value, query, Wv, Woff, Wa, Wo, boff, ba);
    // 2+3) fused: v = value@Wv^T+bv  AND  [off|attn] = query@Wfa^T+bfa
    gemm_fused12<<<dim3(5, 168), blk, GSMEM>>>(p_vh, p_vl, p_qh, p_ql,
                                               p_Wvh, p_Wvl, p_Wfah, p_Wfal,
                                               bv, p_bfa, p_v, p_oa);
    // 4) fused softmax + bilinear + gather
    msda_sample<<<(MR * HEADS_) / 8, blk>>>(p_v, refp, p_oa, p_th, p_tl);
    // 5) out = tmp @ Wo^T + bo
    gemm_bf<<<dim3(2, 168), blk, GSMEM>>>(p_th, p_tl, p_Woh, p_Wol, bo, out, 256);
}

// round 10
// speedup vs baseline: 1.6762x; 1.0449x over previous
#include <cuda_runtime.h>
#include <cuda_bf16.h>
#include <stdint.h>
#include <math.h>

// ---------------- problem constants ----------------
#define B_    2
#define NQ_   5376
#define NV_   5376
#define C_    256
#define HEADS_ 8
#define HD_   32
#define NPT   12
#define KD    256
#define MR    10752       // B*NQ
#define NFA   288         // 192 (off) + 96 (attn) fused

// ---------------- scratch ----------------
__device__ float g_v[(size_t)MR * C_];
__device__ float g_oa[(size_t)MR * NFA];
__device__ float g_bfa[NFA];
__device__ __nv_bfloat16 g_val_hi[(size_t)MR * C_];
__device__ __nv_bfloat16 g_val_lo[(size_t)MR * C_];
__device__ __nv_bfloat16 g_q_hi[(size_t)MR * C_];
__device__ __nv_bfloat16 g_q_lo[(size_t)MR * C_];
__device__ __nv_bfloat16 g_tmp_hi[(size_t)MR * C_];
__device__ __nv_bfloat16 g_tmp_lo[(size_t)MR * C_];
__device__ __nv_bfloat16 g_Wv_hi[256 * 256],  g_Wv_lo[256 * 256];
__device__ __nv_bfloat16 g_Wfa_hi[NFA * 256], g_Wfa_lo[NFA * 256];
__device__ __nv_bfloat16 g_Wo_hi[256 * 256],  g_Wo_lo[256 * 256];

// ---------------- helpers ----------------
__device__ __forceinline__ uint32_t smem_u32(const void* p) {
    uint32_t a;
    asm("{ .reg .u64 t; cvta.to.shared.u64 t, %1; cvt.u32.u64 %0, t; }" : "=r"(a) : "l"(p));
    return a;
}
__device__ __forceinline__ uint32_t pack_bf2(float x, float y) {
    uint32_t r;
    asm("cvt.rn.bf16x2.f32 %0, %1, %2;" : "=r"(r) : "f"(y), "f"(x));
    return r;
}
__device__ __forceinline__ void split4(float4 v, uint2& hp, uint2& lp) {
    const uint32_t h01 = pack_bf2(v.x, v.y);
    const uint32_t h23 = pack_bf2(v.z, v.w);
    const float hx = __uint_as_float(h01 << 16);
    const float hy = __uint_as_float(h01 & 0xFFFF0000u);
    const float hz = __uint_as_float(h23 << 16);
    const float hw = __uint_as_float(h23 & 0xFFFF0000u);
    hp = make_uint2(h01, h23);
    lp = make_uint2(pack_bf2(v.x - hx, v.y - hy), pack_bf2(v.z - hz, v.w - hw));
}

#define LDM4(r, addr) \
    asm volatile("ldmatrix.sync.aligned.m8n8.x4.shared.b16 {%0,%1,%2,%3}, [%4];" \
        : "=r"((r)[0]), "=r"((r)[1]), "=r"((r)[2]), "=r"((r)[3]) : "r"(addr))

#define MMA_BF16(d, a, b0, b1) \
    asm volatile("mma.sync.aligned.m16n8k16.row.col.f32.bf16.bf16.f32 " \
        "{%0,%1,%2,%3}, {%4,%5,%6,%7}, {%8,%9}, {%0,%1,%2,%3};" \
        : "+f"((d)[0]), "+f"((d)[1]), "+f"((d)[2]), "+f"((d)[3]) \
        : "r"((a)[0]), "r"((a)[1]), "r"((a)[2]), "r"((a)[3]), "r"(b0), "r"(b1))

#define CPA(dst, src, sz) \
    asm volatile("cp.async.cg.shared.global [%0], [%1], 16, %2;" \
        :: "r"(dst), "l"(src), "r"(sz) : "memory")
#define CPCOMMIT() asm volatile("cp.async.commit_group;" ::: "memory")
#define CPWAIT(n)  asm volatile("cp.async.wait_group %0;" :: "n"(n) : "memory")

// ---------------- fused convert ----------------
#define CN0 (MR * C_ / 4)
#define CN1 (CN0 + MR * C_ / 4)
#define CN2 (CN1 + 256 * 256 / 4)
#define CN3 (CN2 + 192 * 256 / 4)
#define CN4 (CN3 + 96 * 256 / 4)
#define CN5 (CN4 + 256 * 256 / 4)
#define CN6 (CN5 + 72)

__global__ __launch_bounds__(256)
void cvt_all(const float* __restrict__ value, const float* __restrict__ query,
             const float* __restrict__ Wv, const float* __restrict__ Woff,
             const float* __restrict__ Wa, const float* __restrict__ Wo,
             const float* __restrict__ boff, const float* __restrict__ ba)
{
    const int i = blockIdx.x * blockDim.x + threadIdx.x;
    if (i >= CN6) return;

    const float4* src;
    __nv_bfloat16 *hi, *lo;
    int j;
    if (i < CN0)      { src = (const float4*)value; hi = g_val_hi; lo = g_val_lo; j = i; }
    else if (i < CN1) { src = (const float4*)query; hi = g_q_hi;   lo = g_q_lo;   j = i - CN0; }
    else if (i < CN2) { src = (const float4*)Wv;    hi = g_Wv_hi;  lo = g_Wv_lo;  j = i - CN1; }
    else if (i < CN3) { src = (const float4*)Woff;  hi = g_Wfa_hi; lo = g_Wfa_lo; j = i - CN2; }
    else if (i < CN4) { src = (const float4*)Wa;    hi = g_Wfa_hi + 192 * 256;
                        lo = g_Wfa_lo + 192 * 256;  j = i - CN3; }
    else if (i < CN5) { src = (const float4*)Wo;    hi = g_Wo_hi;  lo = g_Wo_lo;  j = i - CN4; }
    else {
        const int k = i - CN5;
        ((float4*)g_bfa)[k] = (k < 48) ? ((const float4*)boff)[k]
                                       : ((const float4*)ba)[k - 48];
        return;
    }
    uint2 hp, lp;
    split4(src[j], hp, lp);
    ((uint2*)hi)[j] = hp;
    ((uint2*)lo)[j] = lp;
}

// ---------------- split-bf16 mma.sync GEMM core ----------------
// BM=64, BN=64, BK=32, 256 threads, 8 warps (2m x 4n), warp tile 32x16
#define S_ 40
#define STG (64 * S_ * 2)              // 5120 B per buffer (A or W, hi or lo)
#define STAGE_B (4 * STG)              // 20480 B per stage
#define GSMEM (2 * STAGE_B)            // 40960 B

__device__ __forceinline__ void gemm_core(
    const __nv_bfloat16* __restrict__ Ahi, const __nv_bfloat16* __restrict__ Alo,
    const __nv_bfloat16* __restrict__ Whi, const __nv_bfloat16* __restrict__ Wlo,
    const float* __restrict__ bias, float* __restrict__ Cc,
    int Ntrue, int bm, int bn, char* smem)
{
    const int tid  = threadIdx.x;
    const int wid  = tid >> 5;
    const int lane = tid & 31;
    const int wm   = wid >> 2;          // 0..1 : 32-row strip
    const int wn   = wid & 3;           // 0..3 : 16-col strip
    const int wrows = Ntrue - bn;

    const uint32_t sb = smem_u32(smem);

    float acc[2][2][4];
    #pragma unroll
    for (int i = 0; i < 2; i++)
        #pragma unroll
        for (int j = 0; j < 2; j++)
            #pragma unroll
            for (int k = 0; k < 4; k++) acc[i][j][k] = 0.f;

    // staging: 256 x 16B chunks per buffer, 1 per thread
    const int prow = tid >> 2;          // 0..63
    const int pcol = (tid & 3) << 3;    // 0,8,16,24
    const uint32_t psd = (prow * S_ + pcol) * 2;

    auto prefetch = [&](int ch, int stg) {
        const int k0 = ch * 32;
        const uint32_t base = sb + stg * STAGE_B;
        const size_t aoff = (size_t)(bm + prow) * KD + k0 + pcol;
        CPA(base + 0 * STG + psd, Ahi + aoff, 16);
        CPA(base + 1 * STG + psd, Alo + aoff, 16);
        const int valid = (prow < wrows) ? 16 : 0;
        const int wr    = (prow < wrows) ? prow : 0;
        const size_t woff = (size_t)(bn + wr) * KD + k0 + pcol;
        CPA(base + 2 * STG + psd, Whi + woff, valid);
        CPA(base + 3 * STG + psd, Wlo + woff, valid);
        CPCOMMIT();
    };

    const int a_row = lane & 15;
    const int a_kc  = (lane & 16) ? 8 : 0;
    const int b_row = (lane & 7) + ((lane & 16) ? 8 : 0);
    const int b_kc  = (lane & 8) ? 8 : 0;

    prefetch(0, 0);

    #pragma unroll 1
    for (int ch = 0; ch < 8; ch++) {
        const int cur = ch & 1;
        if (ch < 7) {
            prefetch(ch + 1, cur ^ 1);
            CPWAIT(1);
        } else {
            CPWAIT(0);
        }
        __syncthreads();

        const uint32_t base = sb + cur * STAGE_B;
        const uint32_t uAhi = base;
        const uint32_t uAlo = base + STG;
        const uint32_t uWhi = base + 2 * STG;
        const uint32_t uWlo = base + 3 * STG;

        #pragma unroll
        for (int ks = 0; ks < 2; ks++) {
            const int kb = ks * 16;
            uint32_t ah[2][4], al[2][4];
            #pragma unroll
            for (int mf = 0; mf < 2; mf++) {
                const int e = (wm * 32 + mf * 16 + a_row) * S_ + kb + a_kc;
                LDM4(ah[mf], uAhi + e * 2);
                LDM4(al[mf], uAlo + e * 2);
            }
            uint32_t bh[4], bl[4];
            {
                const int e = (wn * 16 + b_row) * S_ + kb + b_kc;
                LDM4(bh, uWhi + e * 2);
                LDM4(bl, uWlo + e * 2);
            }
            #pragma unroll
            for (int mf = 0; mf < 2; mf++) {
                MMA_BF16(acc[mf][0], ah[mf], bh[0], bh[1]);
                MMA_BF16(acc[mf][1], ah[mf], bh[2], bh[3]);
                MMA_BF16(acc[mf][0], ah[mf], bl[0], bl[1]);
                MMA_BF16(acc[mf][1], ah[mf], bl[2], bl[3]);
                MMA_BF16(acc[mf][0], al[mf], bh[0], bh[1]);
                MMA_BF16(acc[mf][1], al[mf], bh[2], bh[3]);
            }
        }
        __syncthreads();
    }

    const int grp  = lane >> 2;
    const int tid4 = lane & 3;
    #pragma unroll
    for (int mf = 0; mf < 2; mf++) {
        const int row0 = bm + wm * 32 + mf * 16 + grp;
        #pragma unroll
        for (int j = 0; j < 2; j++) {
            const int gn = bn + wn * 16 + j * 8 + tid4 * 2;
            if (gn < Ntrue) {
                const float bb0 = bias[gn];
                const float bb1 = bias[gn + 1];
                *(float2*)&Cc[(size_t)row0 * Ntrue + gn] =
                    make_float2(acc[mf][j][0] + bb0, acc[mf][j][1] + bb1);
                *(float2*)&Cc[(size_t)(row0 + 8) * Ntrue + gn] =
                    make_float2(acc[mf][j][2] + bb0, acc[mf][j][3] + bb1);
            }
        }
    }
}

// fused GEMM1+GEMM2: grid.x in [0,9): x<4 -> value-proj (N=256), else off/attn (N=288)
__global__ __launch_bounds__(256, 5)
void gemm_fused12(const __nv_bfloat16* __restrict__ vh, const __nv_bfloat16* __restrict__ vl,
                  const __nv_bfloat16* __restrict__ qh, const __nv_bfloat16* __restrict__ ql,
                  const __nv_bfloat16* __restrict__ Wvh, const __nv_bfloat16* __restrict__ Wvl,
                  const __nv_bfloat16* __restrict__ Wfah, const __nv_bfloat16* __restrict__ Wfal,
                  const float* __restrict__ bv, const float* __restrict__ bfa,
                  float* __restrict__ outv, float* __restrict__ outoa)
{
    extern __shared__ __align__(16) char smem[];
    const int bm = blockIdx.y * 64;
    if (blockIdx.x < 4) {
        gemm_core(vh, vl, Wvh, Wvl, bv, outv, 256, bm, blockIdx.x * 64, smem);
    } else {
        gemm_core(qh, ql, Wfah, Wfal, bfa, outoa, NFA, bm, (blockIdx.x - 4) * 64, smem);
    }
}

__global__ __launch_bounds__(256, 5)
void gemm_bf(const __nv_bfloat16* __restrict__ Ahi, const __nv_bfloat16* __restrict__ Alo,
             const __nv_bfloat16* __restrict__ Whi, const __nv_bfloat16* __restrict__ Wlo,
             const float* __restrict__ bias, float* __restrict__ Cc, int Ntrue)
{
    extern __shared__ __align__(16) char smem[];
    gemm_core(Ahi, Alo, Whi, Wlo, bias, Cc, Ntrue, blockIdx.y * 64, blockIdx.x * 64, smem);
}

// ---------------- fused sampling ----------------
__global__ __launch_bounds__(256)
void msda_sample(const float* __restrict__ v, const float* __restrict__ ref,
                 const float* __restrict__ oa,
                 __nv_bfloat16* __restrict__ out_hi, __nv_bfloat16* __restrict__ out_lo)
{
    __shared__ int2 spk[8][NPT][4];
    const int wslot = threadIdx.x >> 5;
    const int lane  = threadIdx.x & 31;
    const int warp  = blockIdx.x * 8 + wslot;
    const int head  = warp & 7;
    const int bq    = warp >> 3;
    const int b     = bq / NQ_;

    float lg = -1e30f;
    if (lane < NPT) lg = oa[(size_t)bq * NFA + 192 + head * NPT + lane];
    float mx = lg;
    #pragma unroll
    for (int o = 16; o; o >>= 1) mx = fmaxf(mx, __shfl_xor_sync(0xFFFFFFFFu, mx, o));
    float e = (lane < NPT) ? __expf(lg - mx) : 0.f;
    float s = e;
    #pragma unroll
    for (int o = 16; o; o >>= 1) s += __shfl_xor_sync(0xFFFFFFFFu, s, o);

    if (lane < NPT) {
        const float aw  = e / s;
        const int lvl   = lane >> 2;
        const int Hs    = 64 >> lvl;
        const int Wsz   = Hs;
        const int start = (lvl == 0) ? 0 : (lvl == 1) ? 4096 : 5120;
        const float rx = ref[(size_t)bq * 2 + 0];
        const float ry = ref[(size_t)bq * 2 + 1];
        const float ox = oa[(size_t)bq * NFA + head * 24 + lane * 2 + 0];
        const float oy = oa[(size_t)bq * NFA + head * 24 + lane * 2 + 1];
        const float lx = fminf(fmaxf(rx + ox, 0.f), 1.f);
        const float ly = fminf(fmaxf(ry + oy, 0.f), 1.f);
        const float x = lx * (float)Wsz - 0.5f;
        const float y = ly * (float)Hs - 0.5f;
        const float x0f = floorf(x);
        const float y0f = floorf(y);
        const float wx1 = x - x0f;
        const float wy1 = y - y0f;
        const int x0 = (int)x0f;
        const int y0 = (int)y0f;
        const int vb = (b * NV_ + start) * C_ + head * HD_;
        #pragma unroll
        for (int dy = 0; dy < 2; dy++) {
            #pragma unroll
            for (int dx = 0; dx < 2; dx++) {
                const int ix = x0 + dx;
                const int iy = y0 + dy;
                const float w = (dx ? wx1 : 1.f - wx1) * (dy ? wy1 : 1.f - wy1);
                const bool valid = (ix >= 0) & (ix < Wsz) & (iy >= 0) & (iy < Hs);
                const int cx = min(max(ix, 0), Wsz - 1);
                const int cy = min(max(iy, 0), Hs - 1);
                spk[wslot][lane][dy * 2 + dx] =
                    make_int2(vb + (cy * Wsz + cx) * C_,
                              __float_as_int(valid ? (w * aw) : 0.f));
            }
        }
    }
    __syncwarp();

    const int c = lane >> 3;
    const int g = lane & 7;
    float4 acc = make_float4(0.f, 0.f, 0.f, 0.f);
    #pragma unroll
    for (int p = 0; p < NPT; p++) {
        const int2 iw = spk[wslot][p][c];
        const float w = __int_as_float(iw.y);
        const float4 val = __ldg((const float4*)(v + iw.x) + g);
        acc.x = fmaf(w, val.x, acc.x);
        acc.y = fmaf(w, val.y, acc.y);
        acc.z = fmaf(w, val.z, acc.z);
        acc.w = fmaf(w, val.w, acc.w);
    }
    #pragma unroll
    for (int o = 8; o <= 16; o <<= 1) {
        acc.x += __shfl_xor_sync(0xFFFFFFFFu, acc.x, o);
        acc.y += __shfl_xor_sync(0xFFFFFFFFu, acc.y, o);
        acc.z += __shfl_xor_sync(0xFFFFFFFFu, acc.z, o);
        acc.w += __shfl_xor_sync(0xFFFFFFFFu, acc.w, o);
    }
    if (c == 0) {
        uint2 hp, lp;
        split4(acc, hp, lp);
        const size_t eo = ((size_t)bq * C_ + head * HD_ + g * 4) >> 2;
        ((uint2*)out_hi)[eo] = hp;
        ((uint2*)out_lo)[eo] = lp;
    }
}

// ---------------- launch ----------------
extern "C" void kernel_launch(void* const* d_in, const int* in_sizes, int n_in,
                              void* d_out, int out_size)
{
    const float* query = (const float*)d_in[0];
    const float* refp  = (const float*)d_in[1];
    const float* value = (const float*)d_in[2];
    const float* Wv    = (const float*)d_in[3];
    const float* bv    = (const float*)d_in[4];
    const float* Woff  = (const float*)d_in[5];
    const float* boff  = (const float*)d_in[6];
    const float* Wa    = (const float*)d_in[7];
    const float* ba    = (const float*)d_in[8];
    const float* Wo    = (const float*)d_in[9];
    const float* bo    = (const float*)d_in[10];
    float* out = (float*)d_out;

    float *p_v, *p_oa, *p_bfa;
    __nv_bfloat16 *p_vh, *p_vl, *p_qh, *p_ql, *p_th, *p_tl;
    __nv_bfloat16 *p_Wvh, *p_Wvl, *p_Wfah, *p_Wfal, *p_Woh, *p_Wol;
    cudaGetSymbolAddress((void**)&p_v,    g_v);
    cudaGetSymbolAddress((void**)&p_oa,   g_oa);
    cudaGetSymbolAddress((void**)&p_bfa,  g_bfa);
    cudaGetSymbolAddress((void**)&p_vh,   g_val_hi);
    cudaGetSymbolAddress((void**)&p_vl,   g_val_lo);
    cudaGetSymbolAddress((void**)&p_qh,   g_q_hi);
    cudaGetSymbolAddress((void**)&p_ql,   g_q_lo);
    cudaGetSymbolAddress((void**)&p_th,   g_tmp_hi);
    cudaGetSymbolAddress((void**)&p_tl,   g_tmp_lo);
    cudaGetSymbolAddress((void**)&p_Wvh,  g_Wv_hi);
    cudaGetSymbolAddress((void**)&p_Wvl,  g_Wv_lo);
    cudaGetSymbolAddress((void**)&p_Wfah, g_Wfa_hi);
    cudaGetSymbolAddress((void**)&p_Wfal, g_Wfa_lo);
    cudaGetSymbolAddress((void**)&p_Woh,  g_Wo_hi);
    cudaGetSymbolAddress((void**)&p_Wol,  g_Wo_lo);

    static bool attr_set = false;
    if (!attr_set) {
        cudaFuncSetAttribute(gemm_fused12, cudaFuncAttributeMaxDynamicSharedMemorySize, GSMEM);
        cudaFuncSetAttribute(gemm_fused12, cudaFuncAttributePreferredSharedMemoryCarveout, 100);
        cudaFuncSetAttribute(gemm_bf, cudaFuncAttributeMaxDynamicSharedMemorySize, GSMEM);
        cudaFuncSetAttribute(gemm_bf, cudaFuncAttributePreferredSharedMemoryCarveout, 100);
        attr_set = true;
    }

    const dim3 blk(256);

    // 1) all conversions in one launch
    cvt_all<<<(CN6 + 255) / 256, blk>>>(value, query, Wv, Woff, Wa, Wo, boff, ba);
    // 2+3) fused: v = value@Wv^T+bv  AND  [off|attn] = query@Wfa^T+bfa
    gemm_fused12<<<dim3(9, 168), blk, GSMEM>>>(p_vh, p_vl, p_qh, p_ql,
                                               p_Wvh, p_Wvl, p_Wfah, p_Wfal,
                                               bv, p_bfa, p_v, p_oa);
    // 4) fused softmax + bilinear + gather
    msda_sample<<<(MR * HEADS_) / 8, blk>>>(p_v, refp, p_oa, p_th, p_tl);
    // 5) out = tmp @ Wo^T + bo
    gemm_bf<<<dim3(4, 168), blk, GSMEM>>>(p_th, p_tl, p_Woh, p_Wol, bo, out, 256);
}